// round 15
// baseline (speedup 1.0000x reference)
#include <cuda_runtime.h>
#include <cuda_fp16.h>
#include <math.h>
#include <stdint.h>

#define Bn 2
#define Sn 2048
#define Dn 2048
#define Hn 16
#define HDn 128
#define Tn (Bn*Sn)
#define En 8
#define KKn 2
#define Fn 4096

// fp32 scratch
__device__ float g_q[Tn*Dn];
__device__ float g_k[Tn*Dn];
__device__ float g_v[Tn*Dn];
__device__ float g_x1[Tn*Dn];
__device__ float g_h2[Tn*Dn];
__device__ float g_ffn[(size_t)Tn*KKn*Dn];
// fp16 scratch
__device__ __half g_h1h[Tn*Dn];
__device__ __half g_h2h[Tn*Dn];
__device__ __half g_ctxh[Tn*Dn];
__device__ __half g_acth[(size_t)Tn*KKn*Fn];
// fp16 attn weights (small; still pre-converted)
__device__ __half g_wqh[Dn*Dn];
__device__ __half g_wkh[Dn*Dn];
__device__ __half g_wvh[Dn*Dn];
__device__ __half g_woh[Dn*Dn];
// routing
__device__ int   g_cnt[En];
__device__ int   g_off[En];
__device__ int   g_run[En];
__device__ int   g_tok_e[Tn*KKn];
__device__ float g_tok_w[Tn*KKn];
__device__ int   g_tok_pos[Tn*KKn];
__device__ int   g_list_tok[Tn*KKn];

__device__ __forceinline__ uint32_t f2tf(float f) {
    uint32_t u;
    asm("cvt.rna.tf32.f32 %0, %1;" : "=r"(u) : "f"(f));
    return u;
}
__device__ __forceinline__ uint32_t smem_u32(const void* p) {
    uint32_t a;
    asm("{ .reg .u64 t; cvta.to.shared.u64 t, %1; cvt.u32.u64 %0, t; }" : "=r"(a) : "l"(p));
    return a;
}
__device__ __forceinline__ void cpa16(uint32_t dst, const void* src) {
    asm volatile("cp.async.cg.shared.global [%0], [%1], 16;" :: "r"(dst), "l"(src));
}
#define CPA_COMMIT() asm volatile("cp.async.commit_group;" ::: "memory")
#define CPA_WAIT2()  asm volatile("cp.async.wait_group 2;" ::: "memory")

__device__ __forceinline__ void ldsm4(uint32_t& r0, uint32_t& r1, uint32_t& r2, uint32_t& r3,
                                      uint32_t addr) {
    asm volatile("ldmatrix.sync.aligned.m8n8.x4.shared.b16 {%0,%1,%2,%3}, [%4];"
                 : "=r"(r0), "=r"(r1), "=r"(r2), "=r"(r3) : "r"(addr));
}
__device__ __forceinline__ void mma16(float* d, const uint32_t* a, const uint32_t* b) {
    asm volatile(
        "mma.sync.aligned.m16n8k16.row.col.f32.f16.f16.f32 "
        "{%0,%1,%2,%3}, {%4,%5,%6,%7}, {%8,%9}, {%0,%1,%2,%3};"
        : "+f"(d[0]), "+f"(d[1]), "+f"(d[2]), "+f"(d[3])
        : "r"(a[0]), "r"(a[1]), "r"(a[2]), "r"(a[3]), "r"(b[0]), "r"(b[1]));
}
__device__ __forceinline__ void mma8(float* d, const uint32_t* a, const uint32_t* b) {
    asm volatile(
        "mma.sync.aligned.m16n8k8.row.col.f32.tf32.tf32.f32 "
        "{%0,%1,%2,%3}, {%4,%5,%6,%7}, {%8,%9}, {%0,%1,%2,%3};"
        : "+f"(d[0]), "+f"(d[1]), "+f"(d[2]), "+f"(d[3])
        : "r"(a[0]), "r"(a[1]), "r"(a[2]), "r"(a[3]), "r"(b[0]), "r"(b[1]));
}
__device__ __forceinline__ uint4 pack8(float4 a, float4 b) {
    __half2 h0 = __floats2half2_rn(a.x, a.y);
    __half2 h1 = __floats2half2_rn(a.z, a.w);
    __half2 h2 = __floats2half2_rn(b.x, b.y);
    __half2 h3 = __floats2half2_rn(b.z, b.w);
    return make_uint4(*(uint32_t*)&h0, *(uint32_t*)&h1, *(uint32_t*)&h2, *(uint32_t*)&h3);
}

// ---------------- weight conversion fp32 -> fp16 (STG.128; attn weights only) ----------------
__global__ void k_cvt(const float4* __restrict__ src, uint4* __restrict__ dst, int n8) {
    int i = blockIdx.x * 256 + threadIdx.x;
    if (i < n8) dst[i] = pack8(src[2 * i], src[2 * i + 1]);
}

// ---------------- RMSNorm (fp16 out + optional fp32 out) ----------------
__global__ void k_rmsnorm_h(const float* __restrict__ x, const float* __restrict__ w,
                            __half2* __restrict__ outh, float* __restrict__ outf) {
    int row = blockIdx.x;
    const float* xr = x + (size_t)row * Dn;
    float ss = 0.f;
    for (int i = threadIdx.x; i < Dn; i += 256) { float v = xr[i]; ss += v * v; }
    __shared__ float sh[256];
    sh[threadIdx.x] = ss;
    __syncthreads();
    for (int o = 128; o > 0; o >>= 1) {
        if (threadIdx.x < o) sh[threadIdx.x] += sh[threadIdx.x + o];
        __syncthreads();
    }
    float inv = rsqrtf(sh[0] / (float)Dn + 1e-6f);
    __half2* oh = outh + (size_t)row * (Dn / 2);
    float* of = outf ? outf + (size_t)row * Dn : nullptr;
    for (int i = threadIdx.x; i < Dn / 2; i += 256) {
        float a = xr[2 * i] * inv * w[2 * i];
        float b = xr[2 * i + 1] * inv * w[2 * i + 1];
        oh[i] = __floats2half2_rn(a, b);
        if (of) { of[2 * i] = a; of[2 * i + 1] = b; }
    }
}

// ============================================================================
// fp16-input GEMM (cp.async 4-stage + ldmatrix): C = A @ B^T (+R)
// CTA 128x128x32, 8 warps 64x32. z selects among 3 (B,C) pairs.
// ============================================================================
#define GEMM_SMEM (4 * 20480)
__global__ __launch_bounds__(256, 2) void k_h_gemm3(
    const __half* __restrict__ A,
    const __half* __restrict__ B0, const __half* __restrict__ B1, const __half* __restrict__ B2,
    float* __restrict__ C0, float* __restrict__ C1, float* __restrict__ C2,
    const float* __restrict__ R, int M, int ldC, int K) {
    extern __shared__ char dyn[];
    uint32_t sb = smem_u32(dyn);
    int z = blockIdx.z;
    const __half* B = (z == 0) ? B0 : (z == 1) ? B1 : B2;
    float* C = (z == 0) ? C0 : (z == 1) ? C1 : C2;
    int tid = threadIdx.x, lane = tid & 31, w = tid >> 5;
    int wm = w >> 2, wn = w & 3;
    int g = lane >> 2, t = lane & 3;
    int m0 = blockIdx.y * 128, n0 = blockIdx.x * 128;
    uint32_t aAddr = sb + (uint32_t)(wm * 64 + (lane & 15)) * 80 + (lane >> 4) * 16;
    uint32_t bAddr = sb + 10240 + (uint32_t)(wn * 32 + (lane & 15)) * 80 + (lane >> 4) * 16;

#define G3_ISSUE(c, slot) { \
    int k0_ = (c) * 32; \
    uint32_t base_ = sb + (slot) * 20480; \
    _Pragma("unroll") \
    for (int i_ = 0; i_ < 2; i_++) { \
        int cid_ = tid + 256 * i_; \
        int row_ = cid_ >> 2, seg_ = cid_ & 3; \
        cpa16(base_ + row_ * 80 + seg_ * 16, A + (size_t)(m0 + row_) * K + k0_ + seg_ * 8); \
        cpa16(base_ + 10240 + row_ * 80 + seg_ * 16, B + (size_t)(n0 + row_) * K + k0_ + seg_ * 8); \
    } }

    int nit = K >> 5;
    G3_ISSUE(0, 0); CPA_COMMIT();
    G3_ISSUE(1, 1); CPA_COMMIT();
    G3_ISSUE(2, 2); CPA_COMMIT();

    float acc[4][4][4] = {};
    for (int it = 0; it < nit; it++) {
        CPA_WAIT2();
        __syncthreads();
        if (it + 3 < nit) { G3_ISSUE(it + 3, (it + 3) & 3); }
        CPA_COMMIT();
        uint32_t stg = (uint32_t)(it & 3) * 20480;
#pragma unroll
        for (int kk = 0; kk < 2; kk++) {
            uint32_t av[4][4], bv[4][2];
#pragma unroll
            for (int mf = 0; mf < 4; mf++)
                ldsm4(av[mf][0], av[mf][1], av[mf][2], av[mf][3], aAddr + stg + mf * 1280 + kk * 32);
#pragma unroll
            for (int np = 0; np < 2; np++) {
                uint32_t r0, r1, r2, r3;
                ldsm4(r0, r1, r2, r3, bAddr + stg + np * 1280 + kk * 32);
                bv[np * 2][0] = r0; bv[np * 2 + 1][0] = r1;
                bv[np * 2][1] = r2; bv[np * 2 + 1][1] = r3;
            }
#pragma unroll
            for (int mf = 0; mf < 4; mf++)
#pragma unroll
                for (int nf = 0; nf < 4; nf++) mma16(acc[mf][nf], av[mf], bv[nf]);
        }
    }
#undef G3_ISSUE
#pragma unroll
    for (int mf = 0; mf < 4; mf++) {
        int r1 = m0 + wm * 64 + mf * 16 + g, r2 = r1 + 8;
#pragma unroll
        for (int nf = 0; nf < 4; nf++) {
            int c = n0 + wn * 32 + nf * 8 + 2 * t;
            float2 v1 = make_float2(acc[mf][nf][0], acc[mf][nf][1]);
            float2 v2 = make_float2(acc[mf][nf][2], acc[mf][nf][3]);
            if (R) {
                float2 q1 = *(const float2*)(R + (size_t)r1 * ldC + c);
                float2 q2 = *(const float2*)(R + (size_t)r2 * ldC + c);
                v1.x += q1.x; v1.y += q1.y; v2.x += q2.x; v2.y += q2.y;
            }
            *(float2*)(C + (size_t)r1 * ldC + c) = v1;
            *(float2*)(C + (size_t)r2 * ldC + c) = v2;
        }
    }
}

// ============================================================================
// MoE GEMM1: act = silu(h@w1^T)*(h@w3^T). A fp16 via cp.async (4-stage);
// B1/B3 fp32 -> in-kernel cvt -> STS (distance-1 register staging).
// ============================================================================
#define MOE1_SMEM (4 * 20480 + 512)
__global__ __launch_bounds__(256, 2) void k_h_moe1(const __half* __restrict__ h2h,
                                                   const float* __restrict__ w1f,
                                                   const float* __restrict__ w3f) {
    int e = blockIdx.z;
    int cnt = g_cnt[e];
    int m0 = blockIdx.y * 128;
    if (m0 >= cnt) return;
    int off = g_off[e];
    int n0 = blockIdx.x * 64;
    const float* B1 = w1f + (size_t)e * Fn * Dn;
    const float* B3 = w3f + (size_t)e * Fn * Dn;
    extern __shared__ char dyn[];
    uint32_t sb = smem_u32(dyn);
    int* toks = (int*)(dyn + 4 * 20480);
    int tid = threadIdx.x, lane = tid & 31, w = tid >> 5;
    int wm = w >> 2, wn = w & 3;
    int g = lane >> 2, t = lane & 3;
    if (tid < 128) toks[tid] = (m0 + tid < cnt) ? g_list_tok[off + m0 + tid] : g_list_tok[off];
    __syncthreads();

    uint32_t aAddr  = sb + (uint32_t)(wm * 64 + (lane & 15)) * 80 + (lane >> 4) * 16;
    uint32_t b1Addr = sb + 10240 + (uint32_t)(wn * 16 + (lane & 15)) * 80 + (lane >> 4) * 16;
    uint32_t b3Addr = b1Addr + 5120;

    int browA = tid >> 2, bseg = tid & 3;   // B unit: row 0..63, seg 0..3
    const float* p1 = B1 + (size_t)(n0 + browA) * Dn + bseg * 8;
    const float* p3 = B3 + (size_t)(n0 + browA) * Dn + bseg * 8;
    uint32_t bStsOff = (uint32_t)browA * 80 + bseg * 16;

#define M1_A_ISSUE(c, slot) { \
    int k0_ = (c) * 32; \
    uint32_t base_ = sb + (slot) * 20480; \
    _Pragma("unroll") \
    for (int i_ = 0; i_ < 2; i_++) { \
        int cid_ = tid + 256 * i_; \
        int row_ = cid_ >> 2, seg_ = cid_ & 3; \
        cpa16(base_ + row_ * 80 + seg_ * 16, h2h + (size_t)toks[row_] * Dn + k0_ + seg_ * 8); \
    } }
#define M1_B_LDG(c) { \
    const float* q1_ = p1 + (c) * 32; \
    const float* q3_ = p3 + (c) * 32; \
    pb1a = *(const float4*)q1_; pb1b = *(const float4*)(q1_ + 4); \
    pb3a = *(const float4*)q3_; pb3b = *(const float4*)(q3_ + 4); }
#define M1_B_STS(slot) { \
    char* base_ = dyn + (slot) * 20480; \
    *(uint4*)(base_ + 10240 + bStsOff) = pack8(pb1a, pb1b); \
    *(uint4*)(base_ + 15360 + bStsOff) = pack8(pb3a, pb3b); }

    int nit = Dn >> 5;
    float4 pb1a, pb1b, pb3a, pb3b;
    // A prologue: 3 stages in flight
    M1_A_ISSUE(0, 0); CPA_COMMIT();
    M1_A_ISSUE(1, 1); CPA_COMMIT();
    M1_A_ISSUE(2, 2); CPA_COMMIT();
    // B prologue: stage 0 in smem, stage 1 in regs
    M1_B_LDG(0); M1_B_STS(0);
    M1_B_LDG(1);

    float aU[4][2][4] = {}, aG[4][2][4] = {};
    for (int it = 0; it < nit; it++) {
        CPA_WAIT2();
        __syncthreads();
        if (it + 3 < nit) { M1_A_ISSUE(it + 3, (it + 3) & 3); }
        CPA_COMMIT();
        if (it + 1 < nit) {
            M1_B_STS((it + 1) & 3);          // B(it+1) regs -> smem (visible at next sync)
            if (it + 2 < nit) M1_B_LDG(it + 2);
        }
        uint32_t stg = (uint32_t)(it & 3) * 20480;
#pragma unroll
        for (int kk = 0; kk < 2; kk++) {
            uint32_t av[4][4], b1v[2][2], b3v[2][2];
#pragma unroll
            for (int mf = 0; mf < 4; mf++)
                ldsm4(av[mf][0], av[mf][1], av[mf][2], av[mf][3], aAddr + stg + mf * 1280 + kk * 32);
            {
                uint32_t r0, r1, r2, r3;
                ldsm4(r0, r1, r2, r3, b1Addr + stg + kk * 32);
                b1v[0][0] = r0; b1v[1][0] = r1; b1v[0][1] = r2; b1v[1][1] = r3;
                ldsm4(r0, r1, r2, r3, b3Addr + stg + kk * 32);
                b3v[0][0] = r0; b3v[1][0] = r1; b3v[0][1] = r2; b3v[1][1] = r3;
            }
#pragma unroll
            for (int mf = 0; mf < 4; mf++)
#pragma unroll
                for (int nf = 0; nf < 2; nf++) {
                    mma16(aU[mf][nf], av[mf], b1v[nf]);
                    mma16(aG[mf][nf], av[mf], b3v[nf]);
                }
        }
    }
#undef M1_A_ISSUE
#undef M1_B_LDG
#undef M1_B_STS
#pragma unroll
    for (int mf = 0; mf < 4; mf++)
#pragma unroll
        for (int half = 0; half < 2; half++) {
            int r = m0 + wm * 64 + mf * 16 + g + half * 8;
            if (r >= cnt) continue;
            __half* dst = g_acth + (size_t)(off + r) * Fn;
#pragma unroll
            for (int nf = 0; nf < 2; nf++) {
                int c = n0 + wn * 16 + nf * 8 + 2 * t;
                float u0 = aU[mf][nf][half * 2], g0 = aG[mf][nf][half * 2];
                float u1 = aU[mf][nf][half * 2 + 1], g1 = aG[mf][nf][half * 2 + 1];
                *(__half2*)(dst + c) = __floats2half2_rn(u0 / (1.f + expf(-u0)) * g0,
                                                         u1 / (1.f + expf(-u1)) * g1);
            }
        }
}

// ============================================================================
// MoE GEMM2: ffn = act @ w2^T. A fp16 cp.async; B fp32 in-kernel cvt.
// ============================================================================
__global__ __launch_bounds__(256, 2) void k_h_moe2(const float* __restrict__ w2f) {
    int e = blockIdx.z;
    int cnt = g_cnt[e];
    int m0 = blockIdx.y * 128;
    if (m0 >= cnt) return;
    int off = g_off[e];
    int n0 = blockIdx.x * 128;
    const __half* A = g_acth + (size_t)off * Fn;
    const float* B = w2f + (size_t)e * Dn * Fn;
    extern __shared__ char dyn[];
    uint32_t sb = smem_u32(dyn);
    int tid = threadIdx.x, lane = tid & 31, w = tid >> 5;
    int wm = w >> 2, wn = w & 3;
    int g = lane >> 2, t = lane & 3;
    uint32_t aAddr = sb + (uint32_t)(wm * 64 + (lane & 15)) * 80 + (lane >> 4) * 16;
    uint32_t bAddr = sb + 10240 + (uint32_t)(wn * 32 + (lane & 15)) * 80 + (lane >> 4) * 16;

    // two B units per thread: rows 0..127, segs 0..3
    int brow0 = tid >> 2, bseg0 = tid & 3;
    int brow1 = (tid + 256) >> 2, bseg1 = (tid + 256) & 3;
    const float* pB0 = B + (size_t)(n0 + brow0) * Fn + bseg0 * 8;
    const float* pB1 = B + (size_t)(n0 + brow1) * Fn + bseg1 * 8;
    uint32_t bOff0 = (uint32_t)brow0 * 80 + bseg0 * 16;
    uint32_t bOff1 = (uint32_t)brow1 * 80 + bseg1 * 16;

#define M2_A_ISSUE(c, slot) { \
    int k0_ = (c) * 32; \
    uint32_t base_ = sb + (slot) * 20480; \
    _Pragma("unroll") \
    for (int i_ = 0; i_ < 2; i_++) { \
        int cid_ = tid + 256 * i_; \
        int row_ = cid_ >> 2, seg_ = cid_ & 3; \
        int ar_ = min(m0 + row_, cnt - 1); \
        cpa16(base_ + row_ * 80 + seg_ * 16, A + (size_t)ar_ * Fn + k0_ + seg_ * 8); \
    } }
#define M2_B_LDG(c) { \
    const float* q0_ = pB0 + (c) * 32; \
    const float* q1_ = pB1 + (c) * 32; \
    pba0 = *(const float4*)q0_; pba1 = *(const float4*)(q0_ + 4); \
    pbb0 = *(const float4*)q1_; pbb1 = *(const float4*)(q1_ + 4); }
#define M2_B_STS(slot) { \
    char* base_ = dyn + (slot) * 20480 + 10240; \
    *(uint4*)(base_ + bOff0) = pack8(pba0, pba1); \
    *(uint4*)(base_ + bOff1) = pack8(pbb0, pbb1); }

    int nit = Fn >> 5;
    float4 pba0, pba1, pbb0, pbb1;
    M2_A_ISSUE(0, 0); CPA_COMMIT();
    M2_A_ISSUE(1, 1); CPA_COMMIT();
    M2_A_ISSUE(2, 2); CPA_COMMIT();
    M2_B_LDG(0); M2_B_STS(0);
    M2_B_LDG(1);

    float acc[4][4][4] = {};
    for (int it = 0; it < nit; it++) {
        CPA_WAIT2();
        __syncthreads();
        if (it + 3 < nit) { M2_A_ISSUE(it + 3, (it + 3) & 3); }
        CPA_COMMIT();
        if (it + 1 < nit) {
            M2_B_STS((it + 1) & 3);
            if (it + 2 < nit) M2_B_LDG(it + 2);
        }
        uint32_t stg = (uint32_t)(it & 3) * 20480;
#pragma unroll
        for (int kk = 0; kk < 2; kk++) {
            uint32_t av[4][4], bv[4][2];
#pragma unroll
            for (int mf = 0; mf < 4; mf++)
                ldsm4(av[mf][0], av[mf][1], av[mf][2], av[mf][3], aAddr + stg + mf * 1280 + kk * 32);
#pragma unroll
            for (int np = 0; np < 2; np++) {
                uint32_t r0, r1, r2, r3;
                ldsm4(r0, r1, r2, r3, bAddr + stg + np * 1280 + kk * 32);
                bv[np * 2][0] = r0; bv[np * 2 + 1][0] = r1;
                bv[np * 2][1] = r2; bv[np * 2 + 1][1] = r3;
            }
#pragma unroll
            for (int mf = 0; mf < 4; mf++)
#pragma unroll
                for (int nf = 0; nf < 4; nf++) mma16(acc[mf][nf], av[mf], bv[nf]);
        }
    }
#undef M2_A_ISSUE
#undef M2_B_LDG
#undef M2_B_STS
#pragma unroll
    for (int mf = 0; mf < 4; mf++) {
        int r1 = m0 + wm * 64 + mf * 16 + g, r2 = r1 + 8;
#pragma unroll
        for (int nf = 0; nf < 4; nf++) {
            int c = n0 + wn * 32 + nf * 8 + 2 * t;
            if (r1 < cnt)
                *(float2*)(g_ffn + (size_t)(off + r1) * Dn + c) = make_float2(acc[mf][nf][0], acc[mf][nf][1]);
            if (r2 < cnt)
                *(float2*)(g_ffn + (size_t)(off + r2) * Dn + c) = make_float2(acc[mf][nf][2], acc[mf][nf][3]);
        }
    }
}

// ---------------- RoPE (in place fp32 on q,k) ----------------
__global__ void k_rope(float* __restrict__ q, float* __restrict__ k) {
    int gid = blockIdx.x * 256 + threadIdx.x;
    if (gid >= Tn * Hn * 64) return;
    int i = gid & 63;
    int h = (gid >> 6) & (Hn - 1);
    int t = gid >> 10;
    int s = t & (Sn - 1);
    float inv = powf(10000.0f, -(float)i / 64.0f);
    float ang = (float)s * inv, sn, c;
    sincosf(ang, &sn, &c);
    size_t base = (size_t)t * Dn + h * HDn;
    float q1 = q[base + i], q2 = q[base + i + 64];
    q[base + i]      = q1 * c - q2 * sn;
    q[base + i + 64] = q2 * c + q1 * sn;
    float k1 = k[base + i], k2 = k[base + i + 64];
    k[base + i]      = k1 * c - k2 * sn;
    k[base + i + 64] = k2 * c + k1 * sn;
}

// ============ tf32 mma.sync flash attention (RNA tf32; fp16 ctx out) ============
#define ATT_WORDS (128*132 + 64*132 + 64*136 + 128*68)
__global__ __launch_bounds__(256) void k_attn_mma(const float* __restrict__ q,
                                                  const float* __restrict__ k,
                                                  const float* __restrict__ v,
                                                  __half* __restrict__ ctxh) {
    extern __shared__ uint32_t sm[];
    uint32_t* Qs = sm;
    uint32_t* Ks = Qs + 128 * 132;
    uint32_t* Vs = Ks + 64 * 132;
    uint32_t* Ps = Vs + 64 * 136;
    int tid = threadIdx.x, lane = tid & 31, w = tid >> 5;
    int qt = blockIdx.x, bh = blockIdx.y, b = bh >> 4, h = bh & 15;
    int g = lane >> 2, tig = lane & 3;
    const float scale = 0.08838834764831845f;

    for (int i = 0; i < 16; i++) {
        int idx = tid + 256 * i;
        int r = idx >> 5, c4 = idx & 31;
        float4 val = *(const float4*)(q + (size_t)(b * Sn + qt * 128 + r) * Dn + h * HDn + c4 * 4);
        *(uint4*)(Qs + r * 132 + c4 * 4) =
            make_uint4(f2tf(val.x), f2tf(val.y), f2tf(val.z), f2tf(val.w));
    }
    float o_acc[16][4] = {};
    float mrow0 = -1e30f, mrow1 = -1e30f, lrow0 = 0.f, lrow1 = 0.f;
    int wbase = qt * 128 + w * 16;
    int row_hi = wbase + 15;
    int r0g = wbase + g, r1g = r0g + 8;

    int nkt = 2 * qt + 2;
    for (int kt = 0; kt < nkt; kt++) {
        __syncthreads();
        for (int i = 0; i < 8; i++) {
            int idx = tid + 256 * i;
            int r = idx >> 5, c4 = idx & 31;
            size_t gofs = (size_t)(b * Sn + kt * 64 + r) * Dn + h * HDn + c4 * 4;
            float4 kv = *(const float4*)(k + gofs);
            float4 vv = *(const float4*)(v + gofs);
            *(uint4*)(Ks + r * 132 + c4 * 4) =
                make_uint4(f2tf(kv.x), f2tf(kv.y), f2tf(kv.z), f2tf(kv.w));
            *(uint4*)(Vs + r * 136 + c4 * 4) =
                make_uint4(f2tf(vv.x), f2tf(vv.y), f2tf(vv.z), f2tf(vv.w));
        }
        __syncthreads();
        if (kt * 64 > row_hi) continue;

        float sacc[8][4] = {};
#pragma unroll
        for (int kk = 0; kk < 16; kk++) {
            uint32_t av[4];
            const uint32_t* qp = Qs + (w * 16 + g) * 132 + kk * 8 + tig;
            av[0] = qp[0]; av[1] = qp[8 * 132]; av[2] = qp[4]; av[3] = qp[8 * 132 + 4];
#pragma unroll
            for (int nf = 0; nf < 8; nf++) {
                uint32_t bv[2];
                const uint32_t* kp = Ks + (nf * 8 + g) * 132 + kk * 8 + tig;
                bv[0] = kp[0]; bv[1] = kp[4];
                mma8(sacc[nf], av, bv);
            }
        }
        bool need_mask = (kt * 64 + 63) > wbase;
        float mx0 = -1e30f, mx1 = -1e30f;
#pragma unroll
        for (int nf = 0; nf < 8; nf++) {
            int c0 = kt * 64 + nf * 8 + 2 * tig;
#pragma unroll
            for (int j = 0; j < 4; j++) {
                float s = sacc[nf][j] * scale;
                if (need_mask) {
                    int col = c0 + (j & 1);
                    int rg = (j < 2) ? r0g : r1g;
                    if (col > rg) s = -1e30f;
                }
                sacc[nf][j] = s;
                if (j < 2) mx0 = fmaxf(mx0, s); else mx1 = fmaxf(mx1, s);
            }
        }
        mx0 = fmaxf(mx0, __shfl_xor_sync(0xffffffffu, mx0, 1));
        mx0 = fmaxf(mx0, __shfl_xor_sync(0xffffffffu, mx0, 2));
        mx1 = fmaxf(mx1, __shfl_xor_sync(0xffffffffu, mx1, 1));
        mx1 = fmaxf(mx1, __shfl_xor_sync(0xffffffffu, mx1, 2));
        float mn0 = fmaxf(mrow0, mx0), mn1 = fmaxf(mrow1, mx1);
        float a0 = expf(mrow0 - mn0), a1 = expf(mrow1 - mn1);
        mrow0 = mn0; mrow1 = mn1;
        float sum0 = 0.f, sum1 = 0.f;
#pragma unroll
        for (int nf = 0; nf < 8; nf++) {
            float p0 = expf(sacc[nf][0] - mn0), p1 = expf(sacc[nf][1] - mn0);
            float p2 = expf(sacc[nf][2] - mn1), p3 = expf(sacc[nf][3] - mn1);
            sacc[nf][0] = p0; sacc[nf][1] = p1; sacc[nf][2] = p2; sacc[nf][3] = p3;
            sum0 += p0 + p1; sum1 += p2 + p3;
        }
        sum0 += __shfl_xor_sync(0xffffffffu, sum0, 1);
        sum0 += __shfl_xor_sync(0xffffffffu, sum0, 2);
        sum1 += __shfl_xor_sync(0xffffffffu, sum1, 1);
        sum1 += __shfl_xor_sync(0xffffffffu, sum1, 2);
        lrow0 = lrow0 * a0 + sum0;
        lrow1 = lrow1 * a1 + sum1;
#pragma unroll
        for (int nf = 0; nf < 16; nf++) {
            o_acc[nf][0] *= a0; o_acc[nf][1] *= a0;
            o_acc[nf][2] *= a1; o_acc[nf][3] *= a1;
        }
        int pr0 = w * 16 + g;
#pragma unroll
        for (int nf = 0; nf < 8; nf++) {
            int cb = nf * 8 + 2 * tig;
            Ps[pr0 * 68 + cb]           = f2tf(sacc[nf][0]);
            Ps[pr0 * 68 + cb + 1]       = f2tf(sacc[nf][1]);
            Ps[(pr0 + 8) * 68 + cb]     = f2tf(sacc[nf][2]);
            Ps[(pr0 + 8) * 68 + cb + 1] = f2tf(sacc[nf][3]);
        }
        __syncwarp();
#pragma unroll
        for (int kk = 0; kk < 8; kk++) {
            uint32_t av[4];
            const uint32_t* pp = Ps + (w * 16 + g) * 68 + kk * 8 + tig;
            av[0] = pp[0]; av[1] = pp[8 * 68]; av[2] = pp[4]; av[3] = pp[8 * 68 + 4];
#pragma unroll
            for (int nf = 0; nf < 16; nf++) {
                uint32_t bv[2];
                const uint32_t* vp = Vs + (kk * 8 + tig) * 136 + nf * 8 + g;
                bv[0] = vp[0]; bv[1] = vp[4 * 136];
                mma8(o_acc[nf], av, bv);
            }
        }
        __syncwarp();
    }
    float inv0 = 1.f / lrow0, inv1 = 1.f / lrow1;
    size_t ro0 = (size_t)(b * Sn + r0g) * Dn, ro1 = (size_t)(b * Sn + r1g) * Dn;
#pragma unroll
    for (int nf = 0; nf < 16; nf++) {
        int c = h * HDn + nf * 8 + 2 * tig;
        *(__half2*)(ctxh + ro0 + c) = __floats2half2_rn(o_acc[nf][0] * inv0, o_acc[nf][1] * inv0);
        *(__half2*)(ctxh + ro1 + c) = __floats2half2_rn(o_acc[nf][2] * inv1, o_acc[nf][3] * inv1);
    }
}

// ---------------- MoE routing ----------------
__global__ void k_zero() { if (threadIdx.x < En) g_cnt[threadIdx.x] = 0; }

__global__ void k_route(const float* __restrict__ h2, const float* __restrict__ gw) {
    int t = blockIdx.x;
    int lane = threadIdx.x & 31, wid = threadIdx.x >> 5;
    const float* hr = h2 + (size_t)t * Dn;
    const float* gr = gw + (size_t)wid * Dn;
    float s = 0.f;
    for (int i = lane; i < Dn; i += 32) s += hr[i] * gr[i];
    for (int o = 16; o; o >>= 1) s += __shfl_down_sync(0xffffffffu, s, o);
    __shared__ float lg[En];
    if (lane == 0) lg[wid] = s;
    __syncthreads();
    if (threadIdx.x == 0) {
        float mx = lg[0];
        for (int e = 1; e < En; e++) mx = fmaxf(mx, lg[e]);
        float p[En];
        for (int e = 0; e < En; e++) p[e] = expf(lg[e] - mx);
        int i1 = 0;
        for (int e = 1; e < En; e++) if (p[e] > p[i1]) i1 = e;
        int i2 = (i1 == 0) ? 1 : 0;
        for (int e = 0; e < En; e++) { if (e == i1) continue; if (p[e] > p[i2]) i2 = e; }
        float norm = p[i1] + p[i2];
        g_tok_e[t * 2]     = i1; g_tok_w[t * 2]     = p[i1] / norm;
        g_tok_e[t * 2 + 1] = i2; g_tok_w[t * 2 + 1] = p[i2] / norm;
        atomicAdd(&g_cnt[i1], 1);
        atomicAdd(&g_cnt[i2], 1);
    }
}

__global__ void k_scan() {
    if (threadIdx.x == 0) {
        int o = 0;
        for (int e = 0; e < En; e++) { g_off[e] = o; o += g_cnt[e]; g_run[e] = 0; }
    }
}

__global__ void k_place() {
    int t = blockIdx.x * 256 + threadIdx.x;
    if (t >= Tn) return;
    for (int kk = 0; kk < KKn; kk++) {
        int e = g_tok_e[t * 2 + kk];
        int pos = g_off[e] + atomicAdd(&g_run[e], 1);
        g_list_tok[pos] = t;
        g_tok_pos[t * 2 + kk] = pos;
    }
}

// ---------------- final combine ----------------
__global__ void k_final(float* __restrict__ out) {
    int t = blockIdx.x;
    int p0 = g_tok_pos[t * 2], p1 = g_tok_pos[t * 2 + 1];
    float w0 = g_tok_w[t * 2], w1 = g_tok_w[t * 2 + 1];
    const float4* x1 = (const float4*)(g_x1 + (size_t)t * Dn);
    const float4* f0 = (const float4*)(g_ffn + (size_t)p0 * Dn);
    const float4* f1 = (const float4*)(g_ffn + (size_t)p1 * Dn);
    float4* o = (float4*)(out + (size_t)t * Dn);
    for (int c = threadIdx.x; c < Dn / 4; c += 256) {
        float4 a = x1[c], b = f0[c], d = f1[c];
        a.x += w0 * b.x + w1 * d.x;
        a.y += w0 * b.y + w1 * d.y;
        a.z += w0 * b.z + w1 * d.z;
        a.w += w0 * b.w + w1 * d.w;
        o[c] = a;
    }
}

extern "C" void kernel_launch(void* const* d_in, const int* in_sizes, int n_in,
                              void* d_out, int out_size) {
    (void)in_sizes; (void)n_in; (void)out_size;
    const float* x   = (const float*)d_in[0];
    const float* ln1 = (const float*)d_in[3];
    const float* wq  = (const float*)d_in[4];
    const float* wk  = (const float*)d_in[5];
    const float* wv  = (const float*)d_in[6];
    const float* wo  = (const float*)d_in[7];
    const float* ln2 = (const float*)d_in[8];
    const float* gw  = (const float*)d_in[9];
    const float* w1  = (const float*)d_in[10];
    const float* w3  = (const float*)d_in[11];
    const float* w2  = (const float*)d_in[12];
    float* out = (float*)d_out;

    float *qb, *kb, *vb, *x1b, *h2b;
    __half *h1h, *h2h, *ctxh, *wqh, *wkh, *wvh, *woh;
    cudaGetSymbolAddress((void**)&qb,  g_q);
    cudaGetSymbolAddress((void**)&kb,  g_k);
    cudaGetSymbolAddress((void**)&vb,  g_v);
    cudaGetSymbolAddress((void**)&x1b, g_x1);
    cudaGetSymbolAddress((void**)&h2b, g_h2);
    cudaGetSymbolAddress((void**)&h1h, g_h1h);
    cudaGetSymbolAddress((void**)&h2h, g_h2h);
    cudaGetSymbolAddress((void**)&ctxh, g_ctxh);
    cudaGetSymbolAddress((void**)&wqh, g_wqh);
    cudaGetSymbolAddress((void**)&wkh, g_wkh);
    cudaGetSymbolAddress((void**)&wvh, g_wvh);
    cudaGetSymbolAddress((void**)&woh, g_woh);

    const int smem_attn = ATT_WORDS * 4;
    cudaFuncSetAttribute(k_attn_mma, cudaFuncAttributeMaxDynamicSharedMemorySize, smem_attn);
    cudaFuncSetAttribute(k_h_gemm3, cudaFuncAttributeMaxDynamicSharedMemorySize, GEMM_SMEM);
    cudaFuncSetAttribute(k_h_moe1, cudaFuncAttributeMaxDynamicSharedMemorySize, MOE1_SMEM);
    cudaFuncSetAttribute(k_h_moe2, cudaFuncAttributeMaxDynamicSharedMemorySize, GEMM_SMEM);

    // attn weight conversions only (4 launches) + rmsnorm -> qkv lands at ncu slot 6
    const int NW8 = Dn * Dn / 8;
    k_cvt<<<(NW8 + 255) / 256, 256>>>((const float4*)wq, (uint4*)wqh, NW8);
    k_cvt<<<(NW8 + 255) / 256, 256>>>((const float4*)wk, (uint4*)wkh, NW8);
    k_cvt<<<(NW8 + 255) / 256, 256>>>((const float4*)wv, (uint4*)wvh, NW8);
    k_cvt<<<(NW8 + 255) / 256, 256>>>((const float4*)wo, (uint4*)woh, NW8);

    k_rmsnorm_h<<<Tn, 256>>>(x, ln1, (__half2*)h1h, nullptr);
    dim3 gqkv(Dn / 128, Tn / 128, 3);
    k_h_gemm3<<<gqkv, 256, GEMM_SMEM>>>(h1h, wqh, wkh, wvh, qb, kb, vb, nullptr, Tn, Dn, Dn);
    k_rope<<<(Tn * Hn * 64) / 256, 256>>>(qb, kb);
    dim3 ga(Sn / 128, Bn * Hn);
    k_attn_mma<<<ga, 256, smem_attn>>>(qb, kb, vb, ctxh);
    dim3 go(Dn / 128, Tn / 128, 1);
    k_h_gemm3<<<go, 256, GEMM_SMEM>>>(ctxh, woh, woh, woh, x1b, x1b, x1b, x, Tn, Dn, Dn);
    k_rmsnorm_h<<<Tn, 256>>>(x1b, ln2, (__half2*)h2h, h2b);
    k_zero<<<1, 32>>>();
    k_route<<<Tn, 256>>>(h2b, gw);
    k_scan<<<1, 32>>>();
    k_place<<<Tn / 256, 256>>>();
    dim3 gm1(Fn / 64, Tn / 128, En);
    k_h_moe1<<<gm1, 256, MOE1_SMEM>>>(h2h, w1, w3);
    dim3 gm2(Dn / 128, Tn / 128, En);
    k_h_moe2<<<gm2, 256, GEMM_SMEM>>>(w2);
    k_final<<<Tn, 256>>>(out);
}

// round 16
// speedup vs baseline: 1.0848x; 1.0848x over previous
#include <cuda_runtime.h>
#include <cuda_fp16.h>
#include <math.h>
#include <stdint.h>

#define Bn 2
#define Sn 2048
#define Dn 2048
#define Hn 16
#define HDn 128
#define Tn (Bn*Sn)
#define En 8
#define KKn 2
#define Fn 4096

// fp32 scratch
__device__ float g_q[Tn*Dn];
__device__ float g_k[Tn*Dn];
__device__ float g_v[Tn*Dn];
__device__ float g_x1[Tn*Dn];
__device__ float g_h2[Tn*Dn];
__device__ float g_ffn[(size_t)Tn*KKn*Dn];
// fp16 scratch
__device__ __half g_h1h[Tn*Dn];
__device__ __half g_h2h[Tn*Dn];
__device__ __half g_ctxh[Tn*Dn];
__device__ __half g_acth[(size_t)Tn*KKn*Fn];
// fp16 weights
__device__ __half g_wqh[Dn*Dn];
__device__ __half g_wkh[Dn*Dn];
__device__ __half g_wvh[Dn*Dn];
__device__ __half g_woh[Dn*Dn];
__device__ __half g_w1h[(size_t)En*Fn*Dn];
__device__ __half g_w3h[(size_t)En*Fn*Dn];
__device__ __half g_w2h[(size_t)En*Dn*Fn];
// routing
__device__ int   g_cnt[En];
__device__ int   g_off[En];
__device__ int   g_run[En];
__device__ int   g_tok_e[Tn*KKn];
__device__ float g_tok_w[Tn*KKn];
__device__ int   g_tok_pos[Tn*KKn];
__device__ int   g_list_tok[Tn*KKn];

__device__ __forceinline__ uint32_t f2tf(float f) {
    uint32_t u;
    asm("cvt.rna.tf32.f32 %0, %1;" : "=r"(u) : "f"(f));
    return u;
}
__device__ __forceinline__ uint32_t smem_u32(const void* p) {
    uint32_t a;
    asm("{ .reg .u64 t; cvta.to.shared.u64 t, %1; cvt.u32.u64 %0, t; }" : "=r"(a) : "l"(p));
    return a;
}
__device__ __forceinline__ void cpa16(uint32_t dst, const void* src) {
    asm volatile("cp.async.cg.shared.global [%0], [%1], 16;" :: "r"(dst), "l"(src));
}
#define CPA_COMMIT() asm volatile("cp.async.commit_group;" ::: "memory")
#define CPA_WAIT2()  asm volatile("cp.async.wait_group 2;" ::: "memory")

__device__ __forceinline__ void ldsm4(uint32_t& r0, uint32_t& r1, uint32_t& r2, uint32_t& r3,
                                      uint32_t addr) {
    asm volatile("ldmatrix.sync.aligned.m8n8.x4.shared.b16 {%0,%1,%2,%3}, [%4];"
                 : "=r"(r0), "=r"(r1), "=r"(r2), "=r"(r3) : "r"(addr));
}
__device__ __forceinline__ void mma16(float* d, const uint32_t* a, const uint32_t* b) {
    asm volatile(
        "mma.sync.aligned.m16n8k16.row.col.f32.f16.f16.f32 "
        "{%0,%1,%2,%3}, {%4,%5,%6,%7}, {%8,%9}, {%0,%1,%2,%3};"
        : "+f"(d[0]), "+f"(d[1]), "+f"(d[2]), "+f"(d[3])
        : "r"(a[0]), "r"(a[1]), "r"(a[2]), "r"(a[3]), "r"(b[0]), "r"(b[1]));
}
__device__ __forceinline__ void mma8(float* d, const uint32_t* a, const uint32_t* b) {
    asm volatile(
        "mma.sync.aligned.m16n8k8.row.col.f32.tf32.tf32.f32 "
        "{%0,%1,%2,%3}, {%4,%5,%6,%7}, {%8,%9}, {%0,%1,%2,%3};"
        : "+f"(d[0]), "+f"(d[1]), "+f"(d[2]), "+f"(d[3])
        : "r"(a[0]), "r"(a[1]), "r"(a[2]), "r"(a[3]), "r"(b[0]), "r"(b[1]));
}

// ---------------- weight conversion fp32 -> fp16 (STG.128) ----------------
__global__ void k_cvt(const float4* __restrict__ src, uint4* __restrict__ dst, int n8) {
    int i = blockIdx.x * 256 + threadIdx.x;
    if (i < n8) {
        float4 a = src[2 * i], b = src[2 * i + 1];
        __half2 h0 = __floats2half2_rn(a.x, a.y);
        __half2 h1 = __floats2half2_rn(a.z, a.w);
        __half2 h2 = __floats2half2_rn(b.x, b.y);
        __half2 h3 = __floats2half2_rn(b.z, b.w);
        dst[i] = make_uint4(*(uint32_t*)&h0, *(uint32_t*)&h1,
                            *(uint32_t*)&h2, *(uint32_t*)&h3);
    }
}

// ---------------- RMSNorm (fp16 out + optional fp32 out) ----------------
__global__ void k_rmsnorm_h(const float* __restrict__ x, const float* __restrict__ w,
                            __half2* __restrict__ outh, float* __restrict__ outf) {
    int row = blockIdx.x;
    const float* xr = x + (size_t)row * Dn;
    float ss = 0.f;
    for (int i = threadIdx.x; i < Dn; i += 256) { float v = xr[i]; ss += v * v; }
    __shared__ float sh[256];
    sh[threadIdx.x] = ss;
    __syncthreads();
    for (int o = 128; o > 0; o >>= 1) {
        if (threadIdx.x < o) sh[threadIdx.x] += sh[threadIdx.x + o];
        __syncthreads();
    }
    float inv = rsqrtf(sh[0] / (float)Dn + 1e-6f);
    __half2* oh = outh + (size_t)row * (Dn / 2);
    float* of = outf ? outf + (size_t)row * Dn : nullptr;
    for (int i = threadIdx.x; i < Dn / 2; i += 256) {
        float a = xr[2 * i] * inv * w[2 * i];
        float b = xr[2 * i + 1] * inv * w[2 * i + 1];
        oh[i] = __floats2half2_rn(a, b);
        if (of) { of[2 * i] = a; of[2 * i + 1] = b; }
    }
}

// ============================================================================
// fp16-input GEMM (cp.async 4-stage + ldmatrix): C = A @ B^T (+R)
// CTA 128x128x32, 8 warps 64x32. z selects among 3 (B,C) pairs.
// ============================================================================
#define GEMM_SMEM (4 * 20480)
__global__ __launch_bounds__(256, 2) void k_h_gemm3(
    const __half* __restrict__ A,
    const __half* __restrict__ B0, const __half* __restrict__ B1, const __half* __restrict__ B2,
    float* __restrict__ C0, float* __restrict__ C1, float* __restrict__ C2,
    const float* __restrict__ R, int M, int ldC, int K) {
    extern __shared__ char dyn[];
    uint32_t sb = smem_u32(dyn);
    int z = blockIdx.z;
    const __half* B = (z == 0) ? B0 : (z == 1) ? B1 : B2;
    float* C = (z == 0) ? C0 : (z == 1) ? C1 : C2;
    int tid = threadIdx.x, lane = tid & 31, w = tid >> 5;
    int wm = w >> 2, wn = w & 3;
    int g = lane >> 2, t = lane & 3;
    int m0 = blockIdx.y * 128, n0 = blockIdx.x * 128;
    uint32_t aAddr = sb + (uint32_t)(wm * 64 + (lane & 15)) * 80 + (lane >> 4) * 16;
    uint32_t bAddr = sb + 10240 + (uint32_t)(wn * 32 + (lane & 15)) * 80 + (lane >> 4) * 16;

#define G3_ISSUE(c, slot) { \
    int k0_ = (c) * 32; \
    uint32_t base_ = sb + (slot) * 20480; \
    _Pragma("unroll") \
    for (int i_ = 0; i_ < 2; i_++) { \
        int cid_ = tid + 256 * i_; \
        int row_ = cid_ >> 2, seg_ = cid_ & 3; \
        cpa16(base_ + row_ * 80 + seg_ * 16, A + (size_t)(m0 + row_) * K + k0_ + seg_ * 8); \
        cpa16(base_ + 10240 + row_ * 80 + seg_ * 16, B + (size_t)(n0 + row_) * K + k0_ + seg_ * 8); \
    } }

    int nit = K >> 5;
    G3_ISSUE(0, 0); CPA_COMMIT();
    G3_ISSUE(1, 1); CPA_COMMIT();
    G3_ISSUE(2, 2); CPA_COMMIT();

    float acc[4][4][4] = {};
    for (int it = 0; it < nit; it++) {
        CPA_WAIT2();
        __syncthreads();
        if (it + 3 < nit) { G3_ISSUE(it + 3, (it + 3) & 3); }
        CPA_COMMIT();
        uint32_t stg = (uint32_t)(it & 3) * 20480;
#pragma unroll
        for (int kk = 0; kk < 2; kk++) {
            uint32_t av[4][4], bv[4][2];
#pragma unroll
            for (int mf = 0; mf < 4; mf++)
                ldsm4(av[mf][0], av[mf][1], av[mf][2], av[mf][3], aAddr + stg + mf * 1280 + kk * 32);
#pragma unroll
            for (int np = 0; np < 2; np++) {
                uint32_t r0, r1, r2, r3;
                ldsm4(r0, r1, r2, r3, bAddr + stg + np * 1280 + kk * 32);
                bv[np * 2][0] = r0; bv[np * 2 + 1][0] = r1;
                bv[np * 2][1] = r2; bv[np * 2 + 1][1] = r3;
            }
#pragma unroll
            for (int mf = 0; mf < 4; mf++)
#pragma unroll
                for (int nf = 0; nf < 4; nf++) mma16(acc[mf][nf], av[mf], bv[nf]);
        }
    }
#undef G3_ISSUE
#pragma unroll
    for (int mf = 0; mf < 4; mf++) {
        int r1 = m0 + wm * 64 + mf * 16 + g, r2 = r1 + 8;
#pragma unroll
        for (int nf = 0; nf < 4; nf++) {
            int c = n0 + wn * 32 + nf * 8 + 2 * t;
            float2 v1 = make_float2(acc[mf][nf][0], acc[mf][nf][1]);
            float2 v2 = make_float2(acc[mf][nf][2], acc[mf][nf][3]);
            if (R) {
                float2 q1 = *(const float2*)(R + (size_t)r1 * ldC + c);
                float2 q2 = *(const float2*)(R + (size_t)r2 * ldC + c);
                v1.x += q1.x; v1.y += q1.y; v2.x += q2.x; v2.y += q2.y;
            }
            *(float2*)(C + (size_t)r1 * ldC + c) = v1;
            *(float2*)(C + (size_t)r2 * ldC + c) = v2;
        }
    }
}

// ============================================================================
// fp16 MoE GEMM1 (cp.async + ldmatrix): act = silu(h@w1^T)*(h@w3^T)
// ============================================================================
#define MOE1_SMEM (4 * 20480 + 512)
__global__ __launch_bounds__(256, 2) void k_h_moe1(const __half* __restrict__ h2h,
                                                   const __half* __restrict__ w1h,
                                                   const __half* __restrict__ w3h) {
    int e = blockIdx.z;
    int cnt = g_cnt[e];
    int m0 = blockIdx.y * 128;
    if (m0 >= cnt) return;
    int off = g_off[e];
    int n0 = blockIdx.x * 64;
    const __half* B1 = w1h + (size_t)e * Fn * Dn;
    const __half* B3 = w3h + (size_t)e * Fn * Dn;
    extern __shared__ char dyn[];
    uint32_t sb = smem_u32(dyn);
    int* toks = (int*)(dyn + 4 * 20480);
    int tid = threadIdx.x, lane = tid & 31, w = tid >> 5;
    int wm = w >> 2, wn = w & 3;
    int g = lane >> 2, t = lane & 3;
    if (tid < 128) toks[tid] = (m0 + tid < cnt) ? g_list_tok[off + m0 + tid] : g_list_tok[off];
    __syncthreads();

    uint32_t aAddr  = sb + (uint32_t)(wm * 64 + (lane & 15)) * 80 + (lane >> 4) * 16;
    uint32_t b1Addr = sb + 10240 + (uint32_t)(wn * 16 + (lane & 15)) * 80 + (lane >> 4) * 16;
    uint32_t b3Addr = b1Addr + 5120;

#define M1_ISSUE(c, slot) { \
    int k0_ = (c) * 32; \
    uint32_t base_ = sb + (slot) * 20480; \
    _Pragma("unroll") \
    for (int i_ = 0; i_ < 2; i_++) { \
        int cid_ = tid + 256 * i_; \
        int row_ = cid_ >> 2, seg_ = cid_ & 3; \
        cpa16(base_ + row_ * 80 + seg_ * 16, h2h + (size_t)toks[row_] * Dn + k0_ + seg_ * 8); \
    } \
    { int cid_ = tid; int row_ = cid_ >> 2, seg_ = cid_ & 3; \
      cpa16(base_ + 10240 + row_ * 80 + seg_ * 16, B1 + (size_t)(n0 + row_) * Dn + k0_ + seg_ * 8); \
      cpa16(base_ + 15360 + row_ * 80 + seg_ * 16, B3 + (size_t)(n0 + row_) * Dn + k0_ + seg_ * 8); } }

    int nit = Dn >> 5;
    M1_ISSUE(0, 0); CPA_COMMIT();
    M1_ISSUE(1, 1); CPA_COMMIT();
    M1_ISSUE(2, 2); CPA_COMMIT();

    float aU[4][2][4] = {}, aG[4][2][4] = {};
    for (int it = 0; it < nit; it++) {
        CPA_WAIT2();
        __syncthreads();
        if (it + 3 < nit) { M1_ISSUE(it + 3, (it + 3) & 3); }
        CPA_COMMIT();
        uint32_t stg = (uint32_t)(it & 3) * 20480;
#pragma unroll
        for (int kk = 0; kk < 2; kk++) {
            uint32_t av[4][4], b1v[2][2], b3v[2][2];
#pragma unroll
            for (int mf = 0; mf < 4; mf++)
                ldsm4(av[mf][0], av[mf][1], av[mf][2], av[mf][3], aAddr + stg + mf * 1280 + kk * 32);
            {
                uint32_t r0, r1, r2, r3;
                ldsm4(r0, r1, r2, r3, b1Addr + stg + kk * 32);
                b1v[0][0] = r0; b1v[1][0] = r1; b1v[0][1] = r2; b1v[1][1] = r3;
                ldsm4(r0, r1, r2, r3, b3Addr + stg + kk * 32);
                b3v[0][0] = r0; b3v[1][0] = r1; b3v[0][1] = r2; b3v[1][1] = r3;
            }
#pragma unroll
            for (int mf = 0; mf < 4; mf++)
#pragma unroll
                for (int nf = 0; nf < 2; nf++) {
                    mma16(aU[mf][nf], av[mf], b1v[nf]);
                    mma16(aG[mf][nf], av[mf], b3v[nf]);
                }
        }
    }
#undef M1_ISSUE
#pragma unroll
    for (int mf = 0; mf < 4; mf++)
#pragma unroll
        for (int half = 0; half < 2; half++) {
            int r = m0 + wm * 64 + mf * 16 + g + half * 8;
            if (r >= cnt) continue;
            __half* dst = g_acth + (size_t)(off + r) * Fn;
#pragma unroll
            for (int nf = 0; nf < 2; nf++) {
                int c = n0 + wn * 16 + nf * 8 + 2 * t;
                float u0 = aU[mf][nf][half * 2], g0 = aG[mf][nf][half * 2];
                float u1 = aU[mf][nf][half * 2 + 1], g1 = aG[mf][nf][half * 2 + 1];
                *(__half2*)(dst + c) = __floats2half2_rn(u0 / (1.f + expf(-u0)) * g0,
                                                         u1 / (1.f + expf(-u1)) * g1);
            }
        }
}

// ============================================================================
// fp16 MoE GEMM2 (cp.async + ldmatrix): ffn = act @ w2^T. CTA 128x128x32.
// ============================================================================
__global__ __launch_bounds__(256, 2) void k_h_moe2(const __half* __restrict__ w2h) {
    int e = blockIdx.z;
    int cnt = g_cnt[e];
    int m0 = blockIdx.y * 128;
    if (m0 >= cnt) return;
    int off = g_off[e];
    int n0 = blockIdx.x * 128;
    const __half* A = g_acth + (size_t)off * Fn;
    const __half* B = w2h + (size_t)e * Dn * Fn;
    extern __shared__ char dyn[];
    uint32_t sb = smem_u32(dyn);
    int tid = threadIdx.x, lane = tid & 31, w = tid >> 5;
    int wm = w >> 2, wn = w & 3;
    int g = lane >> 2, t = lane & 3;
    uint32_t aAddr = sb + (uint32_t)(wm * 64 + (lane & 15)) * 80 + (lane >> 4) * 16;
    uint32_t bAddr = sb + 10240 + (uint32_t)(wn * 32 + (lane & 15)) * 80 + (lane >> 4) * 16;

#define M2_ISSUE(c, slot) { \
    int k0_ = (c) * 32; \
    uint32_t base_ = sb + (slot) * 20480; \
    _Pragma("unroll") \
    for (int i_ = 0; i_ < 2; i_++) { \
        int cid_ = tid + 256 * i_; \
        int row_ = cid_ >> 2, seg_ = cid_ & 3; \
        int ar_ = min(m0 + row_, cnt - 1); \
        cpa16(base_ + row_ * 80 + seg_ * 16, A + (size_t)ar_ * Fn + k0_ + seg_ * 8); \
        cpa16(base_ + 10240 + row_ * 80 + seg_ * 16, B + (size_t)(n0 + row_) * Fn + k0_ + seg_ * 8); \
    } }

    int nit = Fn >> 5;
    M2_ISSUE(0, 0); CPA_COMMIT();
    M2_ISSUE(1, 1); CPA_COMMIT();
    M2_ISSUE(2, 2); CPA_COMMIT();

    float acc[4][4][4] = {};
    for (int it = 0; it < nit; it++) {
        CPA_WAIT2();
        __syncthreads();
        if (it + 3 < nit) { M2_ISSUE(it + 3, (it + 3) & 3); }
        CPA_COMMIT();
        uint32_t stg = (uint32_t)(it & 3) * 20480;
#pragma unroll
        for (int kk = 0; kk < 2; kk++) {
            uint32_t av[4][4], bv[4][2];
#pragma unroll
            for (int mf = 0; mf < 4; mf++)
                ldsm4(av[mf][0], av[mf][1], av[mf][2], av[mf][3], aAddr + stg + mf * 1280 + kk * 32);
#pragma unroll
            for (int np = 0; np < 2; np++) {
                uint32_t r0, r1, r2, r3;
                ldsm4(r0, r1, r2, r3, bAddr + stg + np * 1280 + kk * 32);
                bv[np * 2][0] = r0; bv[np * 2 + 1][0] = r1;
                bv[np * 2][1] = r2; bv[np * 2 + 1][1] = r3;
            }
#pragma unroll
            for (int mf = 0; mf < 4; mf++)
#pragma unroll
                for (int nf = 0; nf < 4; nf++) mma16(acc[mf][nf], av[mf], bv[nf]);
        }
    }
#undef M2_ISSUE
#pragma unroll
    for (int mf = 0; mf < 4; mf++) {
        int r1 = m0 + wm * 64 + mf * 16 + g, r2 = r1 + 8;
#pragma unroll
        for (int nf = 0; nf < 4; nf++) {
            int c = n0 + wn * 32 + nf * 8 + 2 * t;
            if (r1 < cnt)
                *(float2*)(g_ffn + (size_t)(off + r1) * Dn + c) = make_float2(acc[mf][nf][0], acc[mf][nf][1]);
            if (r2 < cnt)
                *(float2*)(g_ffn + (size_t)(off + r2) * Dn + c) = make_float2(acc[mf][nf][2], acc[mf][nf][3]);
        }
    }
}

// ---------------- RoPE: rotate q,k in place AND pre-round q,k,v to tf32 bits ----------------
__global__ void k_rope(float* __restrict__ q, float* __restrict__ k, float* __restrict__ v) {
    int gid = blockIdx.x * 256 + threadIdx.x;
    if (gid >= Tn * Hn * 64) return;
    int i = gid & 63;
    int h = (gid >> 6) & (Hn - 1);
    int t = gid >> 10;
    int s = t & (Sn - 1);
    float inv = powf(10000.0f, -(float)i / 64.0f);
    float ang = (float)s * inv, sn, c;
    sincosf(ang, &sn, &c);
    size_t base = (size_t)t * Dn + h * HDn;
    float q1 = q[base + i], q2 = q[base + i + 64];
    q[base + i]      = __uint_as_float(f2tf(q1 * c - q2 * sn));
    q[base + i + 64] = __uint_as_float(f2tf(q2 * c + q1 * sn));
    float k1 = k[base + i], k2 = k[base + i + 64];
    k[base + i]      = __uint_as_float(f2tf(k1 * c - k2 * sn));
    k[base + i + 64] = __uint_as_float(f2tf(k2 * c + k1 * sn));
    v[base + i]      = __uint_as_float(f2tf(v[base + i]));
    v[base + i + 64] = __uint_as_float(f2tf(v[base + i + 64]));
}

// ============ tf32 mma.sync flash attention (inputs pre-rounded; raw loads) ============
#define ATT_WORDS (128*132 + 64*132 + 64*136 + 128*68)
__global__ __launch_bounds__(256) void k_attn_mma(const float* __restrict__ q,
                                                  const float* __restrict__ k,
                                                  const float* __restrict__ v,
                                                  __half* __restrict__ ctxh) {
    extern __shared__ uint32_t sm[];
    uint32_t* Qs = sm;
    uint32_t* Ks = Qs + 128 * 132;
    uint32_t* Vs = Ks + 64 * 132;
    uint32_t* Ps = Vs + 64 * 136;
    int tid = threadIdx.x, lane = tid & 31, w = tid >> 5;
    int qt = blockIdx.x, bh = blockIdx.y, b = bh >> 4, h = bh & 15;
    int g = lane >> 2, tig = lane & 3;
    const float scale = 0.08838834764831845f;

    for (int i = 0; i < 16; i++) {
        int idx = tid + 256 * i;
        int r = idx >> 5, c4 = idx & 31;
        *(uint4*)(Qs + r * 132 + c4 * 4) =
            *(const uint4*)(q + (size_t)(b * Sn + qt * 128 + r) * Dn + h * HDn + c4 * 4);
    }
    float o_acc[16][4] = {};
    float mrow0 = -1e30f, mrow1 = -1e30f, lrow0 = 0.f, lrow1 = 0.f;
    int wbase = qt * 128 + w * 16;
    int row_hi = wbase + 15;
    int r0g = wbase + g, r1g = r0g + 8;

    int nkt = 2 * qt + 2;
    for (int kt = 0; kt < nkt; kt++) {
        __syncthreads();
        for (int i = 0; i < 8; i++) {
            int idx = tid + 256 * i;
            int r = idx >> 5, c4 = idx & 31;
            size_t gofs = (size_t)(b * Sn + kt * 64 + r) * Dn + h * HDn + c4 * 4;
            *(uint4*)(Ks + r * 132 + c4 * 4) = *(const uint4*)(k + gofs);
            *(uint4*)(Vs + r * 136 + c4 * 4) = *(const uint4*)(v + gofs);
        }
        __syncthreads();
        if (kt * 64 > row_hi) continue;

        float sacc[8][4] = {};
#pragma unroll
        for (int kk = 0; kk < 16; kk++) {
            uint32_t av[4];
            const uint32_t* qp = Qs + (w * 16 + g) * 132 + kk * 8 + tig;
            av[0] = qp[0]; av[1] = qp[8 * 132]; av[2] = qp[4]; av[3] = qp[8 * 132 + 4];
#pragma unroll
            for (int nf = 0; nf < 8; nf++) {
                uint32_t bv[2];
                const uint32_t* kp = Ks + (nf * 8 + g) * 132 + kk * 8 + tig;
                bv[0] = kp[0]; bv[1] = kp[4];
                mma8(sacc[nf], av, bv);
            }
        }
        bool need_mask = (kt * 64 + 63) > wbase;
        float mx0 = -1e30f, mx1 = -1e30f;
#pragma unroll
        for (int nf = 0; nf < 8; nf++) {
            int c0 = kt * 64 + nf * 8 + 2 * tig;
#pragma unroll
            for (int j = 0; j < 4; j++) {
                float s = sacc[nf][j] * scale;
                if (need_mask) {
                    int col = c0 + (j & 1);
                    int rg = (j < 2) ? r0g : r1g;
                    if (col > rg) s = -1e30f;
                }
                sacc[nf][j] = s;
                if (j < 2) mx0 = fmaxf(mx0, s); else mx1 = fmaxf(mx1, s);
            }
        }
        mx0 = fmaxf(mx0, __shfl_xor_sync(0xffffffffu, mx0, 1));
        mx0 = fmaxf(mx0, __shfl_xor_sync(0xffffffffu, mx0, 2));
        mx1 = fmaxf(mx1, __shfl_xor_sync(0xffffffffu, mx1, 1));
        mx1 = fmaxf(mx1, __shfl_xor_sync(0xffffffffu, mx1, 2));
        float mn0 = fmaxf(mrow0, mx0), mn1 = fmaxf(mrow1, mx1);
        float a0 = expf(mrow0 - mn0), a1 = expf(mrow1 - mn1);
        mrow0 = mn0; mrow1 = mn1;
        float sum0 = 0.f, sum1 = 0.f;
#pragma unroll
        for (int nf = 0; nf < 8; nf++) {
            float p0 = expf(sacc[nf][0] - mn0), p1 = expf(sacc[nf][1] - mn0);
            float p2 = expf(sacc[nf][2] - mn1), p3 = expf(sacc[nf][3] - mn1);
            sacc[nf][0] = p0; sacc[nf][1] = p1; sacc[nf][2] = p2; sacc[nf][3] = p3;
            sum0 += p0 + p1; sum1 += p2 + p3;
        }
        sum0 += __shfl_xor_sync(0xffffffffu, sum0, 1);
        sum0 += __shfl_xor_sync(0xffffffffu, sum0, 2);
        sum1 += __shfl_xor_sync(0xffffffffu, sum1, 1);
        sum1 += __shfl_xor_sync(0xffffffffu, sum1, 2);
        lrow0 = lrow0 * a0 + sum0;
        lrow1 = lrow1 * a1 + sum1;
#pragma unroll
        for (int nf = 0; nf < 16; nf++) {
            o_acc[nf][0] *= a0; o_acc[nf][1] *= a0;
            o_acc[nf][2] *= a1; o_acc[nf][3] *= a1;
        }
        int pr0 = w * 16 + g;
#pragma unroll
        for (int nf = 0; nf < 8; nf++) {
            int cb = nf * 8 + 2 * tig;
            Ps[pr0 * 68 + cb]           = f2tf(sacc[nf][0]);
            Ps[pr0 * 68 + cb + 1]       = f2tf(sacc[nf][1]);
            Ps[(pr0 + 8) * 68 + cb]     = f2tf(sacc[nf][2]);
            Ps[(pr0 + 8) * 68 + cb + 1] = f2tf(sacc[nf][3]);
        }
        __syncwarp();
#pragma unroll
        for (int kk = 0; kk < 8; kk++) {
            uint32_t av[4];
            const uint32_t* pp = Ps + (w * 16 + g) * 68 + kk * 8 + tig;
            av[0] = pp[0]; av[1] = pp[8 * 68]; av[2] = pp[4]; av[3] = pp[8 * 68 + 4];
#pragma unroll
            for (int nf = 0; nf < 16; nf++) {
                uint32_t bv[2];
                const uint32_t* vp = Vs + (kk * 8 + tig) * 136 + nf * 8 + g;
                bv[0] = vp[0]; bv[1] = vp[4 * 136];
                mma8(o_acc[nf], av, bv);
            }
        }
        __syncwarp();
    }
    float inv0 = 1.f / lrow0, inv1 = 1.f / lrow1;
    size_t ro0 = (size_t)(b * Sn + r0g) * Dn, ro1 = (size_t)(b * Sn + r1g) * Dn;
#pragma unroll
    for (int nf = 0; nf < 16; nf++) {
        int c = h * HDn + nf * 8 + 2 * tig;
        *(__half2*)(ctxh + ro0 + c) = __floats2half2_rn(o_acc[nf][0] * inv0, o_acc[nf][1] * inv0);
        *(__half2*)(ctxh + ro1 + c) = __floats2half2_rn(o_acc[nf][2] * inv1, o_acc[nf][3] * inv1);
    }
}

// ---------------- MoE routing ----------------
__global__ void k_zero() { if (threadIdx.x < En) g_cnt[threadIdx.x] = 0; }

__global__ void k_route(const float* __restrict__ h2, const float* __restrict__ gw) {
    int t = blockIdx.x;
    int lane = threadIdx.x & 31, wid = threadIdx.x >> 5;
    const float* hr = h2 + (size_t)t * Dn;
    const float* gr = gw + (size_t)wid * Dn;
    float s = 0.f;
    for (int i = lane; i < Dn; i += 32) s += hr[i] * gr[i];
    for (int o = 16; o; o >>= 1) s += __shfl_down_sync(0xffffffffu, s, o);
    __shared__ float lg[En];
    if (lane == 0) lg[wid] = s;
    __syncthreads();
    if (threadIdx.x == 0) {
        float mx = lg[0];
        for (int e = 1; e < En; e++) mx = fmaxf(mx, lg[e]);
        float p[En];
        for (int e = 0; e < En; e++) p[e] = expf(lg[e] - mx);
        int i1 = 0;
        for (int e = 1; e < En; e++) if (p[e] > p[i1]) i1 = e;
        int i2 = (i1 == 0) ? 1 : 0;
        for (int e = 0; e < En; e++) { if (e == i1) continue; if (p[e] > p[i2]) i2 = e; }
        float norm = p[i1] + p[i2];
        g_tok_e[t * 2]     = i1; g_tok_w[t * 2]     = p[i1] / norm;
        g_tok_e[t * 2 + 1] = i2; g_tok_w[t * 2 + 1] = p[i2] / norm;
        atomicAdd(&g_cnt[i1], 1);
        atomicAdd(&g_cnt[i2], 1);
    }
}

__global__ void k_scan() {
    if (threadIdx.x == 0) {
        int o = 0;
        for (int e = 0; e < En; e++) { g_off[e] = o; o += g_cnt[e]; g_run[e] = 0; }
    }
}

__global__ void k_place() {
    int t = blockIdx.x * 256 + threadIdx.x;
    if (t >= Tn) return;
    for (int kk = 0; kk < KKn; kk++) {
        int e = g_tok_e[t * 2 + kk];
        int pos = g_off[e] + atomicAdd(&g_run[e], 1);
        g_list_tok[pos] = t;
        g_tok_pos[t * 2 + kk] = pos;
    }
}

// ---------------- final combine ----------------
__global__ void k_final(float* __restrict__ out) {
    int t = blockIdx.x;
    int p0 = g_tok_pos[t * 2], p1 = g_tok_pos[t * 2 + 1];
    float w0 = g_tok_w[t * 2], w1 = g_tok_w[t * 2 + 1];
    const float4* x1 = (const float4*)(g_x1 + (size_t)t * Dn);
    const float4* f0 = (const float4*)(g_ffn + (size_t)p0 * Dn);
    const float4* f1 = (const float4*)(g_ffn + (size_t)p1 * Dn);
    float4* o = (float4*)(out + (size_t)t * Dn);
    for (int c = threadIdx.x; c < Dn / 4; c += 256) {
        float4 a = x1[c], b = f0[c], d = f1[c];
        a.x += w0 * b.x + w1 * d.x;
        a.y += w0 * b.y + w1 * d.y;
        a.z += w0 * b.z + w1 * d.z;
        a.w += w0 * b.w + w1 * d.w;
        o[c] = a;
    }
}

extern "C" void kernel_launch(void* const* d_in, const int* in_sizes, int n_in,
                              void* d_out, int out_size) {
    (void)in_sizes; (void)n_in; (void)out_size;
    const float* x   = (const float*)d_in[0];
    const float* ln1 = (const float*)d_in[3];
    const float* wq  = (const float*)d_in[4];
    const float* wk  = (const float*)d_in[5];
    const float* wv  = (const float*)d_in[6];
    const float* wo  = (const float*)d_in[7];
    const float* ln2 = (const float*)d_in[8];
    const float* gw  = (const float*)d_in[9];
    const float* w1  = (const float*)d_in[10];
    const float* w3  = (const float*)d_in[11];
    const float* w2  = (const float*)d_in[12];
    float* out = (float*)d_out;

    float *qb, *kb, *vb, *x1b, *h2b;
    __half *h1h, *h2h, *ctxh, *wqh, *wkh, *wvh, *woh, *w1h, *w3h, *w2h;
    cudaGetSymbolAddress((void**)&qb,  g_q);
    cudaGetSymbolAddress((void**)&kb,  g_k);
    cudaGetSymbolAddress((void**)&vb,  g_v);
    cudaGetSymbolAddress((void**)&x1b, g_x1);
    cudaGetSymbolAddress((void**)&h2b, g_h2);
    cudaGetSymbolAddress((void**)&h1h, g_h1h);
    cudaGetSymbolAddress((void**)&h2h, g_h2h);
    cudaGetSymbolAddress((void**)&ctxh, g_ctxh);
    cudaGetSymbolAddress((void**)&wqh, g_wqh);
    cudaGetSymbolAddress((void**)&wkh, g_wkh);
    cudaGetSymbolAddress((void**)&wvh, g_wvh);
    cudaGetSymbolAddress((void**)&woh, g_woh);
    cudaGetSymbolAddress((void**)&w1h, g_w1h);
    cudaGetSymbolAddress((void**)&w3h, g_w3h);
    cudaGetSymbolAddress((void**)&w2h, g_w2h);

    const int smem_attn = ATT_WORDS * 4;
    cudaFuncSetAttribute(k_attn_mma, cudaFuncAttributeMaxDynamicSharedMemorySize, smem_attn);
    cudaFuncSetAttribute(k_h_gemm3, cudaFuncAttributeMaxDynamicSharedMemorySize, GEMM_SMEM);
    cudaFuncSetAttribute(k_h_moe1, cudaFuncAttributeMaxDynamicSharedMemorySize, MOE1_SMEM);
    cudaFuncSetAttribute(k_h_moe2, cudaFuncAttributeMaxDynamicSharedMemorySize, GEMM_SMEM);

    // side stream for MoE weight conversions (created once, reused; first call
    // happens outside graph capture)
    static cudaStream_t s2 = nullptr;
    static cudaEvent_t evF = nullptr, evJ = nullptr;
    if (!s2) {
        cudaStreamCreateWithFlags(&s2, cudaStreamNonBlocking);
        cudaEventCreateWithFlags(&evF, cudaEventDisableTiming);
        cudaEventCreateWithFlags(&evJ, cudaEventDisableTiming);
    }

    const int NW8 = Dn * Dn / 8;
    const int NM8 = En * Fn * Dn / 8;

    // fork: MoE weight conversions run concurrently with the attention block
    cudaEventRecord(evF, 0);
    cudaStreamWaitEvent(s2, evF, 0);
    k_cvt<<<(NM8 + 255) / 256, 256, 0, s2>>>((const float4*)w1, (uint4*)w1h, NM8);
    k_cvt<<<(NM8 + 255) / 256, 256, 0, s2>>>((const float4*)w3, (uint4*)w3h, NM8);
    k_cvt<<<(NM8 + 255) / 256, 256, 0, s2>>>((const float4*)w2, (uint4*)w2h, NM8);
    cudaEventRecord(evJ, s2);

    // main stream: attention path
    k_cvt<<<(NW8 + 255) / 256, 256>>>((const float4*)wq, (uint4*)wqh, NW8);
    k_cvt<<<(NW8 + 255) / 256, 256>>>((const float4*)wk, (uint4*)wkh, NW8);
    k_cvt<<<(NW8 + 255) / 256, 256>>>((const float4*)wv, (uint4*)wvh, NW8);
    k_cvt<<<(NW8 + 255) / 256, 256>>>((const float4*)wo, (uint4*)woh, NW8);

    k_rmsnorm_h<<<Tn, 256>>>(x, ln1, (__half2*)h1h, nullptr);
    dim3 gqkv(Dn / 128, Tn / 128, 3);
    k_h_gemm3<<<gqkv, 256, GEMM_SMEM>>>(h1h, wqh, wkh, wvh, qb, kb, vb, nullptr, Tn, Dn, Dn);
    k_rope<<<(Tn * Hn * 64) / 256, 256>>>(qb, kb, vb);
    dim3 ga(Sn / 128, Bn * Hn);
    k_attn_mma<<<ga, 256, smem_attn>>>(qb, kb, vb, ctxh);
    dim3 go(Dn / 128, Tn / 128, 1);
    k_h_gemm3<<<go, 256, GEMM_SMEM>>>(ctxh, woh, woh, woh, x1b, x1b, x1b, x, Tn, Dn, Dn);
    k_rmsnorm_h<<<Tn, 256>>>(x1b, ln2, (__half2*)h2h, h2b);
    k_zero<<<1, 32>>>();
    k_route<<<Tn, 256>>>(h2b, gw);
    k_scan<<<1, 32>>>();
    k_place<<<Tn / 256, 256>>>();

    // join: MoE weights must be converted before expert GEMMs
    cudaStreamWaitEvent(0, evJ, 0);
    dim3 gm1(Fn / 64, Tn / 128, En);
    k_h_moe1<<<gm1, 256, MOE1_SMEM>>>(h2h, w1h, w3h);
    dim3 gm2(Dn / 128, Tn / 128, En);
    k_h_moe2<<<gm2, 256, GEMM_SMEM>>>(w2h);
    k_final<<<Tn, 256>>>(out);
}

// round 17
// speedup vs baseline: 1.0870x; 1.0021x over previous
#include <cuda_runtime.h>
#include <cuda_fp16.h>
#include <math.h>
#include <stdint.h>

#define Bn 2
#define Sn 2048
#define Dn 2048
#define Hn 16
#define HDn 128
#define Tn (Bn*Sn)
#define En 8
#define KKn 2
#define Fn 4096

// fp32 scratch
__device__ float g_q[Tn*Dn];
__device__ float g_k[Tn*Dn];
__device__ float g_v[Tn*Dn];
__device__ float g_x1[Tn*Dn];
__device__ float g_h2[Tn*Dn];
__device__ float g_ffn[(size_t)Tn*KKn*Dn];
// fp16 scratch
__device__ __half g_h1h[Tn*Dn];
__device__ __half g_h2h[Tn*Dn];
__device__ __half g_ctxh[Tn*Dn];
__device__ __half g_acth[(size_t)Tn*KKn*Fn];
// fp16 weights
__device__ __half g_wqh[Dn*Dn];
__device__ __half g_wkh[Dn*Dn];
__device__ __half g_wvh[Dn*Dn];
__device__ __half g_woh[Dn*Dn];
__device__ __half g_w1h[(size_t)En*Fn*Dn];
__device__ __half g_w3h[(size_t)En*Fn*Dn];
__device__ __half g_w2h[(size_t)En*Dn*Fn];
// routing
__device__ int   g_cnt[En];
__device__ int   g_off[En];
__device__ int   g_run[En];
__device__ int   g_tok_e[Tn*KKn];
__device__ float g_tok_w[Tn*KKn];
__device__ int   g_tok_pos[Tn*KKn];
__device__ int   g_list_tok[Tn*KKn];

__device__ __forceinline__ uint32_t f2tf(float f) {
    uint32_t u;
    asm("cvt.rna.tf32.f32 %0, %1;" : "=r"(u) : "f"(f));
    return u;
}
__device__ __forceinline__ uint32_t smem_u32(const void* p) {
    uint32_t a;
    asm("{ .reg .u64 t; cvta.to.shared.u64 t, %1; cvt.u32.u64 %0, t; }" : "=r"(a) : "l"(p));
    return a;
}
__device__ __forceinline__ void cpa16(uint32_t dst, const void* src) {
    asm volatile("cp.async.cg.shared.global [%0], [%1], 16;" :: "r"(dst), "l"(src));
}
#define CPA_COMMIT() asm volatile("cp.async.commit_group;" ::: "memory")
#define CPA_WAIT2()  asm volatile("cp.async.wait_group 2;" ::: "memory")

__device__ __forceinline__ void ldsm4(uint32_t& r0, uint32_t& r1, uint32_t& r2, uint32_t& r3,
                                      uint32_t addr) {
    asm volatile("ldmatrix.sync.aligned.m8n8.x4.shared.b16 {%0,%1,%2,%3}, [%4];"
                 : "=r"(r0), "=r"(r1), "=r"(r2), "=r"(r3) : "r"(addr));
}
__device__ __forceinline__ void mma16(float* d, const uint32_t* a, const uint32_t* b) {
    asm volatile(
        "mma.sync.aligned.m16n8k16.row.col.f32.f16.f16.f32 "
        "{%0,%1,%2,%3}, {%4,%5,%6,%7}, {%8,%9}, {%0,%1,%2,%3};"
        : "+f"(d[0]), "+f"(d[1]), "+f"(d[2]), "+f"(d[3])
        : "r"(a[0]), "r"(a[1]), "r"(a[2]), "r"(a[3]), "r"(b[0]), "r"(b[1]));
}
__device__ __forceinline__ void mma8(float* d, const uint32_t* a, const uint32_t* b) {
    asm volatile(
        "mma.sync.aligned.m16n8k8.row.col.f32.tf32.tf32.f32 "
        "{%0,%1,%2,%3}, {%4,%5,%6,%7}, {%8,%9}, {%0,%1,%2,%3};"
        : "+f"(d[0]), "+f"(d[1]), "+f"(d[2]), "+f"(d[3])
        : "r"(a[0]), "r"(a[1]), "r"(a[2]), "r"(a[3]), "r"(b[0]), "r"(b[1]));
}

// ---------------- weight conversion fp32 -> fp16 (STG.128) ----------------
__global__ void k_cvt(const float4* __restrict__ src, uint4* __restrict__ dst, int n8) {
    int i = blockIdx.x * 256 + threadIdx.x;
    if (i < n8) {
        float4 a = src[2 * i], b = src[2 * i + 1];
        __half2 h0 = __floats2half2_rn(a.x, a.y);
        __half2 h1 = __floats2half2_rn(a.z, a.w);
        __half2 h2 = __floats2half2_rn(b.x, b.y);
        __half2 h3 = __floats2half2_rn(b.z, b.w);
        dst[i] = make_uint4(*(uint32_t*)&h0, *(uint32_t*)&h1,
                            *(uint32_t*)&h2, *(uint32_t*)&h3);
    }
}

// ---------------- RMSNorm (fp16 out + optional fp32 out) ----------------
__global__ void k_rmsnorm_h(const float* __restrict__ x, const float* __restrict__ w,
                            __half2* __restrict__ outh, float* __restrict__ outf) {
    int row = blockIdx.x;
    const float* xr = x + (size_t)row * Dn;
    float ss = 0.f;
    for (int i = threadIdx.x; i < Dn; i += 256) { float v = xr[i]; ss += v * v; }
    __shared__ float sh[256];
    sh[threadIdx.x] = ss;
    __syncthreads();
    for (int o = 128; o > 0; o >>= 1) {
        if (threadIdx.x < o) sh[threadIdx.x] += sh[threadIdx.x + o];
        __syncthreads();
    }
    float inv = rsqrtf(sh[0] / (float)Dn + 1e-6f);
    __half2* oh = outh + (size_t)row * (Dn / 2);
    float* of = outf ? outf + (size_t)row * Dn : nullptr;
    for (int i = threadIdx.x; i < Dn / 2; i += 256) {
        float a = xr[2 * i] * inv * w[2 * i];
        float b = xr[2 * i + 1] * inv * w[2 * i + 1];
        oh[i] = __floats2half2_rn(a, b);
        if (of) { of[2 * i] = a; of[2 * i + 1] = b; }
    }
}

// ============================================================================
// fp16-input GEMM (cp.async 4-stage + ldmatrix): C = A @ B^T (+R)
// CTA 128x128x32, 8 warps 64x32. z selects among 3 (B,C) pairs.
// ============================================================================
#define GEMM_SMEM (4 * 20480)
__global__ __launch_bounds__(256, 2) void k_h_gemm3(
    const __half* __restrict__ A,
    const __half* __restrict__ B0, const __half* __restrict__ B1, const __half* __restrict__ B2,
    float* __restrict__ C0, float* __restrict__ C1, float* __restrict__ C2,
    const float* __restrict__ R, int M, int ldC, int K) {
    extern __shared__ char dyn[];
    uint32_t sb = smem_u32(dyn);
    int z = blockIdx.z;
    const __half* B = (z == 0) ? B0 : (z == 1) ? B1 : B2;
    float* C = (z == 0) ? C0 : (z == 1) ? C1 : C2;
    int tid = threadIdx.x, lane = tid & 31, w = tid >> 5;
    int wm = w >> 2, wn = w & 3;
    int g = lane >> 2, t = lane & 3;
    int m0 = blockIdx.y * 128, n0 = blockIdx.x * 128;
    uint32_t aAddr = sb + (uint32_t)(wm * 64 + (lane & 15)) * 80 + (lane >> 4) * 16;
    uint32_t bAddr = sb + 10240 + (uint32_t)(wn * 32 + (lane & 15)) * 80 + (lane >> 4) * 16;

#define G3_ISSUE(c, slot) { \
    int k0_ = (c) * 32; \
    uint32_t base_ = sb + (slot) * 20480; \
    _Pragma("unroll") \
    for (int i_ = 0; i_ < 2; i_++) { \
        int cid_ = tid + 256 * i_; \
        int row_ = cid_ >> 2, seg_ = cid_ & 3; \
        cpa16(base_ + row_ * 80 + seg_ * 16, A + (size_t)(m0 + row_) * K + k0_ + seg_ * 8); \
        cpa16(base_ + 10240 + row_ * 80 + seg_ * 16, B + (size_t)(n0 + row_) * K + k0_ + seg_ * 8); \
    } }

    int nit = K >> 5;
    G3_ISSUE(0, 0); CPA_COMMIT();
    G3_ISSUE(1, 1); CPA_COMMIT();
    G3_ISSUE(2, 2); CPA_COMMIT();

    float acc[4][4][4] = {};
    for (int it = 0; it < nit; it++) {
        CPA_WAIT2();
        __syncthreads();
        if (it + 3 < nit) { G3_ISSUE(it + 3, (it + 3) & 3); }
        CPA_COMMIT();
        uint32_t stg = (uint32_t)(it & 3) * 20480;
#pragma unroll
        for (int kk = 0; kk < 2; kk++) {
            uint32_t av[4][4], bv[4][2];
#pragma unroll
            for (int mf = 0; mf < 4; mf++)
                ldsm4(av[mf][0], av[mf][1], av[mf][2], av[mf][3], aAddr + stg + mf * 1280 + kk * 32);
#pragma unroll
            for (int np = 0; np < 2; np++) {
                uint32_t r0, r1, r2, r3;
                ldsm4(r0, r1, r2, r3, bAddr + stg + np * 1280 + kk * 32);
                bv[np * 2][0] = r0; bv[np * 2 + 1][0] = r1;
                bv[np * 2][1] = r2; bv[np * 2 + 1][1] = r3;
            }
#pragma unroll
            for (int mf = 0; mf < 4; mf++)
#pragma unroll
                for (int nf = 0; nf < 4; nf++) mma16(acc[mf][nf], av[mf], bv[nf]);
        }
    }
#undef G3_ISSUE
#pragma unroll
    for (int mf = 0; mf < 4; mf++) {
        int r1 = m0 + wm * 64 + mf * 16 + g, r2 = r1 + 8;
#pragma unroll
        for (int nf = 0; nf < 4; nf++) {
            int c = n0 + wn * 32 + nf * 8 + 2 * t;
            float2 v1 = make_float2(acc[mf][nf][0], acc[mf][nf][1]);
            float2 v2 = make_float2(acc[mf][nf][2], acc[mf][nf][3]);
            if (R) {
                float2 q1 = *(const float2*)(R + (size_t)r1 * ldC + c);
                float2 q2 = *(const float2*)(R + (size_t)r2 * ldC + c);
                v1.x += q1.x; v1.y += q1.y; v2.x += q2.x; v2.y += q2.y;
            }
            *(float2*)(C + (size_t)r1 * ldC + c) = v1;
            *(float2*)(C + (size_t)r2 * ldC + c) = v2;
        }
    }
}

// ============================================================================
// fp16 MoE GEMM1 (cp.async + ldmatrix): act = silu(h@w1^T)*(h@w3^T)
// ============================================================================
#define MOE1_SMEM (4 * 20480 + 512)
__global__ __launch_bounds__(256, 2) void k_h_moe1(const __half* __restrict__ h2h,
                                                   const __half* __restrict__ w1h,
                                                   const __half* __restrict__ w3h) {
    int e = blockIdx.z;
    int cnt = g_cnt[e];
    int m0 = blockIdx.y * 128;
    if (m0 >= cnt) return;
    int off = g_off[e];
    int n0 = blockIdx.x * 64;
    const __half* B1 = w1h + (size_t)e * Fn * Dn;
    const __half* B3 = w3h + (size_t)e * Fn * Dn;
    extern __shared__ char dyn[];
    uint32_t sb = smem_u32(dyn);
    int* toks = (int*)(dyn + 4 * 20480);
    int tid = threadIdx.x, lane = tid & 31, w = tid >> 5;
    int wm = w >> 2, wn = w & 3;
    int g = lane >> 2, t = lane & 3;
    if (tid < 128) toks[tid] = (m0 + tid < cnt) ? g_list_tok[off + m0 + tid] : g_list_tok[off];
    __syncthreads();

    uint32_t aAddr  = sb + (uint32_t)(wm * 64 + (lane & 15)) * 80 + (lane >> 4) * 16;
    uint32_t b1Addr = sb + 10240 + (uint32_t)(wn * 16 + (lane & 15)) * 80 + (lane >> 4) * 16;
    uint32_t b3Addr = b1Addr + 5120;

#define M1_ISSUE(c, slot) { \
    int k0_ = (c) * 32; \
    uint32_t base_ = sb + (slot) * 20480; \
    _Pragma("unroll") \
    for (int i_ = 0; i_ < 2; i_++) { \
        int cid_ = tid + 256 * i_; \
        int row_ = cid_ >> 2, seg_ = cid_ & 3; \
        cpa16(base_ + row_ * 80 + seg_ * 16, h2h + (size_t)toks[row_] * Dn + k0_ + seg_ * 8); \
    } \
    { int cid_ = tid; int row_ = cid_ >> 2, seg_ = cid_ & 3; \
      cpa16(base_ + 10240 + row_ * 80 + seg_ * 16, B1 + (size_t)(n0 + row_) * Dn + k0_ + seg_ * 8); \
      cpa16(base_ + 15360 + row_ * 80 + seg_ * 16, B3 + (size_t)(n0 + row_) * Dn + k0_ + seg_ * 8); } }

    int nit = Dn >> 5;
    M1_ISSUE(0, 0); CPA_COMMIT();
    M1_ISSUE(1, 1); CPA_COMMIT();
    M1_ISSUE(2, 2); CPA_COMMIT();

    float aU[4][2][4] = {}, aG[4][2][4] = {};
    for (int it = 0; it < nit; it++) {
        CPA_WAIT2();
        __syncthreads();
        if (it + 3 < nit) { M1_ISSUE(it + 3, (it + 3) & 3); }
        CPA_COMMIT();
        uint32_t stg = (uint32_t)(it & 3) * 20480;
#pragma unroll
        for (int kk = 0; kk < 2; kk++) {
            uint32_t av[4][4], b1v[2][2], b3v[2][2];
#pragma unroll
            for (int mf = 0; mf < 4; mf++)
                ldsm4(av[mf][0], av[mf][1], av[mf][2], av[mf][3], aAddr + stg + mf * 1280 + kk * 32);
            {
                uint32_t r0, r1, r2, r3;
                ldsm4(r0, r1, r2, r3, b1Addr + stg + kk * 32);
                b1v[0][0] = r0; b1v[1][0] = r1; b1v[0][1] = r2; b1v[1][1] = r3;
                ldsm4(r0, r1, r2, r3, b3Addr + stg + kk * 32);
                b3v[0][0] = r0; b3v[1][0] = r1; b3v[0][1] = r2; b3v[1][1] = r3;
            }
#pragma unroll
            for (int mf = 0; mf < 4; mf++)
#pragma unroll
                for (int nf = 0; nf < 2; nf++) {
                    mma16(aU[mf][nf], av[mf], b1v[nf]);
                    mma16(aG[mf][nf], av[mf], b3v[nf]);
                }
        }
    }
#undef M1_ISSUE
#pragma unroll
    for (int mf = 0; mf < 4; mf++)
#pragma unroll
        for (int half = 0; half < 2; half++) {
            int r = m0 + wm * 64 + mf * 16 + g + half * 8;
            if (r >= cnt) continue;
            __half* dst = g_acth + (size_t)(off + r) * Fn;
#pragma unroll
            for (int nf = 0; nf < 2; nf++) {
                int c = n0 + wn * 16 + nf * 8 + 2 * t;
                float u0 = aU[mf][nf][half * 2], g0 = aG[mf][nf][half * 2];
                float u1 = aU[mf][nf][half * 2 + 1], g1 = aG[mf][nf][half * 2 + 1];
                *(__half2*)(dst + c) = __floats2half2_rn(u0 / (1.f + __expf(-u0)) * g0,
                                                         u1 / (1.f + __expf(-u1)) * g1);
            }
        }
}

// ============================================================================
// fp16 MoE GEMM2 (cp.async + ldmatrix): ffn = act @ w2^T. CTA 128x128x32.
// ============================================================================
__global__ __launch_bounds__(256, 2) void k_h_moe2(const __half* __restrict__ w2h) {
    int e = blockIdx.z;
    int cnt = g_cnt[e];
    int m0 = blockIdx.y * 128;
    if (m0 >= cnt) return;
    int off = g_off[e];
    int n0 = blockIdx.x * 128;
    const __half* A = g_acth + (size_t)off * Fn;
    const __half* B = w2h + (size_t)e * Dn * Fn;
    extern __shared__ char dyn[];
    uint32_t sb = smem_u32(dyn);
    int tid = threadIdx.x, lane = tid & 31, w = tid >> 5;
    int wm = w >> 2, wn = w & 3;
    int g = lane >> 2, t = lane & 3;
    uint32_t aAddr = sb + (uint32_t)(wm * 64 + (lane & 15)) * 80 + (lane >> 4) * 16;
    uint32_t bAddr = sb + 10240 + (uint32_t)(wn * 32 + (lane & 15)) * 80 + (lane >> 4) * 16;

#define M2_ISSUE(c, slot) { \
    int k0_ = (c) * 32; \
    uint32_t base_ = sb + (slot) * 20480; \
    _Pragma("unroll") \
    for (int i_ = 0; i_ < 2; i_++) { \
        int cid_ = tid + 256 * i_; \
        int row_ = cid_ >> 2, seg_ = cid_ & 3; \
        int ar_ = min(m0 + row_, cnt - 1); \
        cpa16(base_ + row_ * 80 + seg_ * 16, A + (size_t)ar_ * Fn + k0_ + seg_ * 8); \
        cpa16(base_ + 10240 + row_ * 80 + seg_ * 16, B + (size_t)(n0 + row_) * Fn + k0_ + seg_ * 8); \
    } }

    int nit = Fn >> 5;
    M2_ISSUE(0, 0); CPA_COMMIT();
    M2_ISSUE(1, 1); CPA_COMMIT();
    M2_ISSUE(2, 2); CPA_COMMIT();

    float acc[4][4][4] = {};
    for (int it = 0; it < nit; it++) {
        CPA_WAIT2();
        __syncthreads();
        if (it + 3 < nit) { M2_ISSUE(it + 3, (it + 3) & 3); }
        CPA_COMMIT();
        uint32_t stg = (uint32_t)(it & 3) * 20480;
#pragma unroll
        for (int kk = 0; kk < 2; kk++) {
            uint32_t av[4][4], bv[4][2];
#pragma unroll
            for (int mf = 0; mf < 4; mf++)
                ldsm4(av[mf][0], av[mf][1], av[mf][2], av[mf][3], aAddr + stg + mf * 1280 + kk * 32);
#pragma unroll
            for (int np = 0; np < 2; np++) {
                uint32_t r0, r1, r2, r3;
                ldsm4(r0, r1, r2, r3, bAddr + stg + np * 1280 + kk * 32);
                bv[np * 2][0] = r0; bv[np * 2 + 1][0] = r1;
                bv[np * 2][1] = r2; bv[np * 2 + 1][1] = r3;
            }
#pragma unroll
            for (int mf = 0; mf < 4; mf++)
#pragma unroll
                for (int nf = 0; nf < 4; nf++) mma16(acc[mf][nf], av[mf], bv[nf]);
        }
    }
#undef M2_ISSUE
#pragma unroll
    for (int mf = 0; mf < 4; mf++) {
        int r1 = m0 + wm * 64 + mf * 16 + g, r2 = r1 + 8;
#pragma unroll
        for (int nf = 0; nf < 4; nf++) {
            int c = n0 + wn * 32 + nf * 8 + 2 * t;
            if (r1 < cnt)
                *(float2*)(g_ffn + (size_t)(off + r1) * Dn + c) = make_float2(acc[mf][nf][0], acc[mf][nf][1]);
            if (r2 < cnt)
                *(float2*)(g_ffn + (size_t)(off + r2) * Dn + c) = make_float2(acc[mf][nf][2], acc[mf][nf][3]);
        }
    }
}

// ---------------- RoPE: rotate q,k in place AND pre-round q,k,v to tf32 bits ----------------
__global__ void k_rope(float* __restrict__ q, float* __restrict__ k, float* __restrict__ v) {
    int gid = blockIdx.x * 256 + threadIdx.x;
    if (gid >= Tn * Hn * 64) return;
    int i = gid & 63;
    int h = (gid >> 6) & (Hn - 1);
    int t = gid >> 10;
    int s = t & (Sn - 1);
    float inv = powf(10000.0f, -(float)i / 64.0f);
    float ang = (float)s * inv, sn, c;
    sincosf(ang, &sn, &c);
    size_t base = (size_t)t * Dn + h * HDn;
    float q1 = q[base + i], q2 = q[base + i + 64];
    q[base + i]      = __uint_as_float(f2tf(q1 * c - q2 * sn));
    q[base + i + 64] = __uint_as_float(f2tf(q2 * c + q1 * sn));
    float k1 = k[base + i], k2 = k[base + i + 64];
    k[base + i]      = __uint_as_float(f2tf(k1 * c - k2 * sn));
    k[base + i + 64] = __uint_as_float(f2tf(k2 * c + k1 * sn));
    v[base + i]      = __uint_as_float(f2tf(v[base + i]));
    v[base + i + 64] = __uint_as_float(f2tf(v[base + i + 64]));
}

// ============ tf32 mma.sync flash attention (inputs pre-rounded; raw loads) ============
#define ATT_WORDS (128*132 + 64*132 + 64*136 + 128*68)
__global__ __launch_bounds__(256) void k_attn_mma(const float* __restrict__ q,
                                                  const float* __restrict__ k,
                                                  const float* __restrict__ v,
                                                  __half* __restrict__ ctxh) {
    extern __shared__ uint32_t sm[];
    uint32_t* Qs = sm;
    uint32_t* Ks = Qs + 128 * 132;
    uint32_t* Vs = Ks + 64 * 132;
    uint32_t* Ps = Vs + 64 * 136;
    int tid = threadIdx.x, lane = tid & 31, w = tid >> 5;
    int qt = blockIdx.x, bh = blockIdx.y, b = bh >> 4, h = bh & 15;
    int g = lane >> 2, tig = lane & 3;
    const float scale = 0.08838834764831845f;

    for (int i = 0; i < 16; i++) {
        int idx = tid + 256 * i;
        int r = idx >> 5, c4 = idx & 31;
        *(uint4*)(Qs + r * 132 + c4 * 4) =
            *(const uint4*)(q + (size_t)(b * Sn + qt * 128 + r) * Dn + h * HDn + c4 * 4);
    }
    float o_acc[16][4] = {};
    float mrow0 = -1e30f, mrow1 = -1e30f, lrow0 = 0.f, lrow1 = 0.f;
    int wbase = qt * 128 + w * 16;
    int row_hi = wbase + 15;
    int r0g = wbase + g, r1g = r0g + 8;

    int nkt = 2 * qt + 2;
    for (int kt = 0; kt < nkt; kt++) {
        __syncthreads();
        for (int i = 0; i < 8; i++) {
            int idx = tid + 256 * i;
            int r = idx >> 5, c4 = idx & 31;
            size_t gofs = (size_t)(b * Sn + kt * 64 + r) * Dn + h * HDn + c4 * 4;
            *(uint4*)(Ks + r * 132 + c4 * 4) = *(const uint4*)(k + gofs);
            *(uint4*)(Vs + r * 136 + c4 * 4) = *(const uint4*)(v + gofs);
        }
        __syncthreads();
        if (kt * 64 > row_hi) continue;

        float sacc[8][4] = {};
#pragma unroll
        for (int kk = 0; kk < 16; kk++) {
            uint32_t av[4];
            const uint32_t* qp = Qs + (w * 16 + g) * 132 + kk * 8 + tig;
            av[0] = qp[0]; av[1] = qp[8 * 132]; av[2] = qp[4]; av[3] = qp[8 * 132 + 4];
#pragma unroll
            for (int nf = 0; nf < 8; nf++) {
                uint32_t bv[2];
                const uint32_t* kp = Ks + (nf * 8 + g) * 132 + kk * 8 + tig;
                bv[0] = kp[0]; bv[1] = kp[4];
                mma8(sacc[nf], av, bv);
            }
        }
        bool need_mask = (kt * 64 + 63) > wbase;
        float mx0 = -1e30f, mx1 = -1e30f;
#pragma unroll
        for (int nf = 0; nf < 8; nf++) {
            int c0 = kt * 64 + nf * 8 + 2 * tig;
#pragma unroll
            for (int j = 0; j < 4; j++) {
                float s = sacc[nf][j] * scale;
                if (need_mask) {
                    int col = c0 + (j & 1);
                    int rg = (j < 2) ? r0g : r1g;
                    if (col > rg) s = -1e30f;
                }
                sacc[nf][j] = s;
                if (j < 2) mx0 = fmaxf(mx0, s); else mx1 = fmaxf(mx1, s);
            }
        }
        mx0 = fmaxf(mx0, __shfl_xor_sync(0xffffffffu, mx0, 1));
        mx0 = fmaxf(mx0, __shfl_xor_sync(0xffffffffu, mx0, 2));
        mx1 = fmaxf(mx1, __shfl_xor_sync(0xffffffffu, mx1, 1));
        mx1 = fmaxf(mx1, __shfl_xor_sync(0xffffffffu, mx1, 2));
        float mn0 = fmaxf(mrow0, mx0), mn1 = fmaxf(mrow1, mx1);
        float a0 = __expf(mrow0 - mn0), a1 = __expf(mrow1 - mn1);
        mrow0 = mn0; mrow1 = mn1;
        float sum0 = 0.f, sum1 = 0.f;
#pragma unroll
        for (int nf = 0; nf < 8; nf++) {
            float p0 = __expf(sacc[nf][0] - mn0), p1 = __expf(sacc[nf][1] - mn0);
            float p2 = __expf(sacc[nf][2] - mn1), p3 = __expf(sacc[nf][3] - mn1);
            sacc[nf][0] = p0; sacc[nf][1] = p1; sacc[nf][2] = p2; sacc[nf][3] = p3;
            sum0 += p0 + p1; sum1 += p2 + p3;
        }
        sum0 += __shfl_xor_sync(0xffffffffu, sum0, 1);
        sum0 += __shfl_xor_sync(0xffffffffu, sum0, 2);
        sum1 += __shfl_xor_sync(0xffffffffu, sum1, 1);
        sum1 += __shfl_xor_sync(0xffffffffu, sum1, 2);
        lrow0 = lrow0 * a0 + sum0;
        lrow1 = lrow1 * a1 + sum1;
#pragma unroll
        for (int nf = 0; nf < 16; nf++) {
            o_acc[nf][0] *= a0; o_acc[nf][1] *= a0;
            o_acc[nf][2] *= a1; o_acc[nf][3] *= a1;
        }
        int pr0 = w * 16 + g;
#pragma unroll
        for (int nf = 0; nf < 8; nf++) {
            int cb = nf * 8 + 2 * tig;
            Ps[pr0 * 68 + cb]           = f2tf(sacc[nf][0]);
            Ps[pr0 * 68 + cb + 1]       = f2tf(sacc[nf][1]);
            Ps[(pr0 + 8) * 68 + cb]     = f2tf(sacc[nf][2]);
            Ps[(pr0 + 8) * 68 + cb + 1] = f2tf(sacc[nf][3]);
        }
        __syncwarp();
#pragma unroll
        for (int kk = 0; kk < 8; kk++) {
            uint32_t av[4];
            const uint32_t* pp = Ps + (w * 16 + g) * 68 + kk * 8 + tig;
            av[0] = pp[0]; av[1] = pp[8 * 68]; av[2] = pp[4]; av[3] = pp[8 * 68 + 4];
#pragma unroll
            for (int nf = 0; nf < 16; nf++) {
                uint32_t bv[2];
                const uint32_t* vp = Vs + (kk * 8 + tig) * 136 + nf * 8 + g;
                bv[0] = vp[0]; bv[1] = vp[4 * 136];
                mma8(o_acc[nf], av, bv);
            }
        }
        __syncwarp();
    }
    float inv0 = 1.f / lrow0, inv1 = 1.f / lrow1;
    size_t ro0 = (size_t)(b * Sn + r0g) * Dn, ro1 = (size_t)(b * Sn + r1g) * Dn;
#pragma unroll
    for (int nf = 0; nf < 16; nf++) {
        int c = h * HDn + nf * 8 + 2 * tig;
        *(__half2*)(ctxh + ro0 + c) = __floats2half2_rn(o_acc[nf][0] * inv0, o_acc[nf][1] * inv0);
        *(__half2*)(ctxh + ro1 + c) = __floats2half2_rn(o_acc[nf][2] * inv1, o_acc[nf][3] * inv1);
    }
}

// ---------------- MoE routing ----------------
__global__ void k_zero() { if (threadIdx.x < En) g_cnt[threadIdx.x] = 0; }

__global__ void k_route(const float* __restrict__ h2, const float* __restrict__ gw) {
    int t = blockIdx.x;
    int lane = threadIdx.x & 31, wid = threadIdx.x >> 5;
    const float* hr = h2 + (size_t)t * Dn;
    const float* gr = gw + (size_t)wid * Dn;
    float s = 0.f;
    for (int i = lane; i < Dn; i += 32) s += hr[i] * gr[i];
    for (int o = 16; o; o >>= 1) s += __shfl_down_sync(0xffffffffu, s, o);
    __shared__ float lg[En];
    if (lane == 0) lg[wid] = s;
    __syncthreads();
    if (threadIdx.x == 0) {
        float mx = lg[0];
        for (int e = 1; e < En; e++) mx = fmaxf(mx, lg[e]);
        float p[En];
        for (int e = 0; e < En; e++) p[e] = expf(lg[e] - mx);
        int i1 = 0;
        for (int e = 1; e < En; e++) if (p[e] > p[i1]) i1 = e;
        int i2 = (i1 == 0) ? 1 : 0;
        for (int e = 0; e < En; e++) { if (e == i1) continue; if (p[e] > p[i2]) i2 = e; }
        float norm = p[i1] + p[i2];
        g_tok_e[t * 2]     = i1; g_tok_w[t * 2]     = p[i1] / norm;
        g_tok_e[t * 2 + 1] = i2; g_tok_w[t * 2 + 1] = p[i2] / norm;
        atomicAdd(&g_cnt[i1], 1);
        atomicAdd(&g_cnt[i2], 1);
    }
}

__global__ void k_scan() {
    if (threadIdx.x == 0) {
        int o = 0;
        for (int e = 0; e < En; e++) { g_off[e] = o; o += g_cnt[e]; g_run[e] = 0; }
    }
}

__global__ void k_place() {
    int t = blockIdx.x * 256 + threadIdx.x;
    if (t >= Tn) return;
    for (int kk = 0; kk < KKn; kk++) {
        int e = g_tok_e[t * 2 + kk];
        int pos = g_off[e] + atomicAdd(&g_run[e], 1);
        g_list_tok[pos] = t;
        g_tok_pos[t * 2 + kk] = pos;
    }
}

// ---------------- final combine ----------------
__global__ void k_final(float* __restrict__ out) {
    int t = blockIdx.x;
    int p0 = g_tok_pos[t * 2], p1 = g_tok_pos[t * 2 + 1];
    float w0 = g_tok_w[t * 2], w1 = g_tok_w[t * 2 + 1];
    const float4* x1 = (const float4*)(g_x1 + (size_t)t * Dn);
    const float4* f0 = (const float4*)(g_ffn + (size_t)p0 * Dn);
    const float4* f1 = (const float4*)(g_ffn + (size_t)p1 * Dn);
    float4* o = (float4*)(out + (size_t)t * Dn);
    for (int c = threadIdx.x; c < Dn / 4; c += 256) {
        float4 a = x1[c], b = f0[c], d = f1[c];
        a.x += w0 * b.x + w1 * d.x;
        a.y += w0 * b.y + w1 * d.y;
        a.z += w0 * b.z + w1 * d.z;
        a.w += w0 * b.w + w1 * d.w;
        o[c] = a;
    }
}

extern "C" void kernel_launch(void* const* d_in, const int* in_sizes, int n_in,
                              void* d_out, int out_size) {
    (void)in_sizes; (void)n_in; (void)out_size;
    const float* x   = (const float*)d_in[0];
    const float* ln1 = (const float*)d_in[3];
    const float* wq  = (const float*)d_in[4];
    const float* wk  = (const float*)d_in[5];
    const float* wv  = (const float*)d_in[6];
    const float* wo  = (const float*)d_in[7];
    const float* ln2 = (const float*)d_in[8];
    const float* gw  = (const float*)d_in[9];
    const float* w1  = (const float*)d_in[10];
    const float* w3  = (const float*)d_in[11];
    const float* w2  = (const float*)d_in[12];
    float* out = (float*)d_out;

    float *qb, *kb, *vb, *x1b, *h2b;
    __half *h1h, *h2h, *ctxh, *wqh, *wkh, *wvh, *woh, *w1h, *w3h, *w2h;
    cudaGetSymbolAddress((void**)&qb,  g_q);
    cudaGetSymbolAddress((void**)&kb,  g_k);
    cudaGetSymbolAddress((void**)&vb,  g_v);
    cudaGetSymbolAddress((void**)&x1b, g_x1);
    cudaGetSymbolAddress((void**)&h2b, g_h2);
    cudaGetSymbolAddress((void**)&h1h, g_h1h);
    cudaGetSymbolAddress((void**)&h2h, g_h2h);
    cudaGetSymbolAddress((void**)&ctxh, g_ctxh);
    cudaGetSymbolAddress((void**)&wqh, g_wqh);
    cudaGetSymbolAddress((void**)&wkh, g_wkh);
    cudaGetSymbolAddress((void**)&wvh, g_wvh);
    cudaGetSymbolAddress((void**)&woh, g_woh);
    cudaGetSymbolAddress((void**)&w1h, g_w1h);
    cudaGetSymbolAddress((void**)&w3h, g_w3h);
    cudaGetSymbolAddress((void**)&w2h, g_w2h);

    const int smem_attn = ATT_WORDS * 4;
    cudaFuncSetAttribute(k_attn_mma, cudaFuncAttributeMaxDynamicSharedMemorySize, smem_attn);
    cudaFuncSetAttribute(k_h_gemm3, cudaFuncAttributeMaxDynamicSharedMemorySize, GEMM_SMEM);
    cudaFuncSetAttribute(k_h_moe1, cudaFuncAttributeMaxDynamicSharedMemorySize, MOE1_SMEM);
    cudaFuncSetAttribute(k_h_moe2, cudaFuncAttributeMaxDynamicSharedMemorySize, GEMM_SMEM);

    static cudaStream_t s2 = nullptr;
    static cudaEvent_t evF = nullptr, evJ = nullptr;
    if (!s2) {
        cudaStreamCreateWithFlags(&s2, cudaStreamNonBlocking);
        cudaEventCreateWithFlags(&evF, cudaEventDisableTiming);
        cudaEventCreateWithFlags(&evJ, cudaEventDisableTiming);
    }

    const int NW8 = Dn * Dn / 8;
    const int NM8 = En * Fn * Dn / 8;

    // record fork point FIRST (side-stream work submitted later still only
    // depends on this point — submission order reordered for ncu profiling)
    cudaEventRecord(evF, 0);

    // main stream: 4 attn cvts + rmsnorm, then QKV gemm3 = launch #6 (ncu -s 5 -c 1)
    k_cvt<<<(NW8 + 255) / 256, 256>>>((const float4*)wq, (uint4*)wqh, NW8);
    k_cvt<<<(NW8 + 255) / 256, 256>>>((const float4*)wk, (uint4*)wkh, NW8);
    k_cvt<<<(NW8 + 255) / 256, 256>>>((const float4*)wv, (uint4*)wvh, NW8);
    k_cvt<<<(NW8 + 255) / 256, 256>>>((const float4*)wo, (uint4*)woh, NW8);
    k_rmsnorm_h<<<Tn, 256>>>(x, ln1, (__half2*)h1h, nullptr);
    dim3 gqkv(Dn / 128, Tn / 128, 3);
    k_h_gemm3<<<gqkv, 256, GEMM_SMEM>>>(h1h, wqh, wkh, wvh, qb, kb, vb, nullptr, Tn, Dn, Dn);

    // side stream: MoE weight conversions (waits only on entry fork event)
    cudaStreamWaitEvent(s2, evF, 0);
    k_cvt<<<(NM8 + 255) / 256, 256, 0, s2>>>((const float4*)w1, (uint4*)w1h, NM8);
    k_cvt<<<(NM8 + 255) / 256, 256, 0, s2>>>((const float4*)w3, (uint4*)w3h, NM8);
    k_cvt<<<(NM8 + 255) / 256, 256, 0, s2>>>((const float4*)w2, (uint4*)w2h, NM8);
    cudaEventRecord(evJ, s2);

    k_rope<<<(Tn * Hn * 64) / 256, 256>>>(qb, kb, vb);
    dim3 ga(Sn / 128, Bn * Hn);
    k_attn_mma<<<ga, 256, smem_attn>>>(qb, kb, vb, ctxh);
    dim3 go(Dn / 128, Tn / 128, 1);
    k_h_gemm3<<<go, 256, GEMM_SMEM>>>(ctxh, woh, woh, woh, x1b, x1b, x1b, x, Tn, Dn, Dn);
    k_rmsnorm_h<<<Tn, 256>>>(x1b, ln2, (__half2*)h2h, h2b);
    k_zero<<<1, 32>>>();
    k_route<<<Tn, 256>>>(h2b, gw);
    k_scan<<<1, 32>>>();
    k_place<<<Tn / 256, 256>>>();

    // join: MoE weights ready before expert GEMMs
    cudaStreamWaitEvent(0, evJ, 0);
    dim3 gm1(Fn / 64, Tn / 128, En);
    k_h_moe1<<<gm1, 256, MOE1_SMEM>>>(h2h, w1h, w3h);
    dim3 gm2(Dn / 128, Tn / 128, En);
    k_h_moe2<<<gm2, 256, GEMM_SMEM>>>(w2h);
    k_final<<<Tn, 256>>>(out);
}